// round 11
// baseline (speedup 1.0000x reference)
#include <cuda_runtime.h>
#include <cuda_bf16.h>
#include <math.h>

typedef unsigned long long ull;

// ---- scratch ----
__device__ __nv_bfloat16 g_xh[4096*2048], g_xl[4096*2048];   // x split; reused for ctx
__device__ __nv_bfloat16 g_wqkvh[3072*2048], g_wqkvl[3072*2048]; // concat WqT|WkT|WvT
__device__ __nv_bfloat16 g_woh[2048*2048], g_wol[2048*2048];
__device__ __nv_bfloat16 g_qh[4096*2048], g_ql[4096*2048];
__device__ __nv_bfloat16 g_kh[4096*512],  g_kl[4096*512];
__device__ __nv_bfloat16 g_vh[4096*512],  g_vl[4096*512];

#define QSCALE (0.125f * 1.4426950408889634f)   // 1/sqrt(64) * log2(e)

// fp32 -> hi/lo bf16 split
__global__ void __launch_bounds__(256) fsplit(const float4* __restrict__ in,
                                              ull* __restrict__ oh, ull* __restrict__ ol,
                                              int n4, float scale){
    int i = blockIdx.x*blockDim.x + threadIdx.x, st = gridDim.x*blockDim.x;
    for(; i < n4; i += st){
        float4 v = in[i]; float f[4] = {v.x*scale, v.y*scale, v.z*scale, v.w*scale};
        ull h=0,l=0;
#pragma unroll
        for(int j=0;j<4;j++){
            __nv_bfloat16 hb = __float2bfloat16(f[j]);
            __nv_bfloat16 lb = __float2bfloat16(f[j]-__bfloat162float(hb));
            h |= (ull)__bfloat16_as_ushort(hb) << (16*j);
            l |= (ull)__bfloat16_as_ushort(lb) << (16*j);
        }
        oh[i]=h; ol[i]=l;
    }
}

// all 4 weight transposed-splits in one launch
__global__ void wsplitAll(const float* __restrict__ Wq, const float* __restrict__ Wk,
                          const float* __restrict__ Wv, const float* __restrict__ Wo,
                          __nv_bfloat16* __restrict__ qkvh, __nv_bfloat16* __restrict__ qkvl,
                          __nv_bfloat16* __restrict__ woh, __nv_bfloat16* __restrict__ wol){
    __shared__ float t[32][33];
    int bx = blockIdx.x;
    const float* W; __nv_bfloat16 *Th, *Tl; int N, n0;
    if(bx < 64){ W=Wq; Th=qkvh; Tl=qkvl; N=2048; n0=bx*32; }
    else if(bx < 80){ W=Wk; Th=qkvh+(size_t)2048*2048; Tl=qkvl+(size_t)2048*2048; N=512; n0=(bx-64)*32; }
    else if(bx < 96){ W=Wv; Th=qkvh+(size_t)2560*2048; Tl=qkvl+(size_t)2560*2048; N=512; n0=(bx-80)*32; }
    else { W=Wo; Th=woh; Tl=wol; N=2048; n0=(bx-96)*32; }
    int k0 = blockIdx.y*32;
    int tx = threadIdx.x, ty = threadIdx.y;
#pragma unroll
    for(int p=0;p<32;p+=8) t[ty+p][tx] = W[(size_t)(k0+ty+p)*N + n0+tx];
    __syncthreads();
#pragma unroll
    for(int p=0;p<32;p+=8){
        float v = t[tx][ty+p];
        __nv_bfloat16 h = __float2bfloat16(v);
        __nv_bfloat16 l = __float2bfloat16(v-__bfloat162float(h));
        Th[(size_t)(n0+ty+p)*2048 + k0+tx] = h;
        Tl[(size_t)(n0+ty+p)*2048 + k0+tx] = l;
    }
}

// ---- mma helpers ----
__device__ __forceinline__ void ldsm4(unsigned* r, unsigned a){
    asm volatile("ldmatrix.sync.aligned.m8n8.x4.shared.b16 {%0,%1,%2,%3},[%4];"
                 :"=r"(r[0]),"=r"(r[1]),"=r"(r[2]),"=r"(r[3]):"r"(a));
}
__device__ __forceinline__ void ldsm4t(unsigned* r, unsigned a){
    asm volatile("ldmatrix.sync.aligned.m8n8.x4.trans.shared.b16 {%0,%1,%2,%3},[%4];"
                 :"=r"(r[0]),"=r"(r[1]),"=r"(r[2]),"=r"(r[3]):"r"(a));
}
__device__ __forceinline__ void mma16816(float* c, const unsigned* a, const unsigned* b){
    asm volatile("mma.sync.aligned.m16n8k16.row.col.f32.bf16.bf16.f32 "
                 "{%0,%1,%2,%3},{%4,%5,%6,%7},{%8,%9},{%0,%1,%2,%3};"
                 :"+f"(c[0]),"+f"(c[1]),"+f"(c[2]),"+f"(c[3])
                 :"r"(a[0]),"r"(a[1]),"r"(a[2]),"r"(a[3]),"r"(b[0]),"r"(b[1]));
}
__device__ __forceinline__ void cpa16(unsigned d, const void* s){
    asm volatile("cp.async.cg.shared.global [%0],[%1],16;"::"r"(d),"l"(s):"memory");
}
__device__ __forceinline__ void cpcommit(){ asm volatile("cp.async.commit_group;":::"memory"); }
__device__ __forceinline__ unsigned packbf(float lo, float hi){
    unsigned r; asm("cvt.rn.bf16x2.f32 %0, %1, %2;":"=r"(r):"f"(hi),"f"(lo)); return r;
}
__device__ __forceinline__ float ex2f(float x){
    float r; asm("ex2.approx.ftz.f32 %0,%1;":"=f"(r):"f"(x)); return r;
}

// ---------------------------------------------------------------------------
// mma.sync GEMM (verified, unchanged)
// ---------------------------------------------------------------------------
#define SROW 40
#define SMAT (128*SROW)
#define SSTG (4*SMAT)
#define GSMEM (3*SSTG*2)

__global__ void __launch_bounds__(256,1)
gemm_mma(const __nv_bfloat16* __restrict__ Ah, const __nv_bfloat16* __restrict__ Al,
         const __nv_bfloat16* __restrict__ Bh, const __nv_bfloat16* __restrict__ Bl,
         float* __restrict__ Cf,
         __nv_bfloat16* __restrict__ qh, __nv_bfloat16* __restrict__ ql,
         __nv_bfloat16* __restrict__ kh, __nv_bfloat16* __restrict__ kl,
         __nv_bfloat16* __restrict__ vh, __nv_bfloat16* __restrict__ vl){
    extern __shared__ __nv_bfloat16 sm[];
    const unsigned smb = (unsigned)__cvta_generic_to_shared(sm);
    const int tid = threadIdx.x, lane = tid & 31, wid = tid >> 5;
    const int wm = wid >> 1, wn = wid & 1;
    const int bm = blockIdx.y * 128, bn = blockIdx.x * 128;
    const __nv_bfloat16* gsrc[4] = {Ah, Al, Bh, Bl};

    float acc[2][8][4];
#pragma unroll
    for(int i=0;i<2;i++)
#pragma unroll
        for(int j=0;j<8;j++)
#pragma unroll
            for(int q=0;q<4;q++) acc[i][j][q]=0.f;

    unsigned aoff[2], boff[4];
#pragma unroll
    for(int mf=0;mf<2;mf++)
        aoff[mf] = (unsigned)((wm*32 + mf*16 + (lane&7) + ((lane>>3)&1)*8)*(SROW*2) + (lane>>4)*16);
#pragma unroll
    for(int jj=0;jj<4;jj++)
        boff[jj] = (unsigned)((wn*64 + jj*16 + (lane&7) + (lane>>4)*8)*(SROW*2) + ((lane>>3)&1)*16);

    auto load_stage = [&](int s, int k0){
#pragma unroll
        for(int t=0;t<8;t++){
            int c = tid + t*256;
            int g = c >> 9;
            int idx = c & 511;
            int row = idx >> 2, kc = idx & 3;
            int grow = (g < 2 ? bm : bn) + row;
            const __nv_bfloat16* src = gsrc[g] + (size_t)grow*2048 + k0 + kc*8;
            unsigned dst = smb + (unsigned)((s*SSTG + g*SMAT + row*SROW)*2 + kc*16);
            cpa16(dst, src);
        }
        cpcommit();
    };

    load_stage(0, 0);
    load_stage(1, 32);

    for(int ks=0; ks<64; ks++){
        asm volatile("cp.async.wait_group 1;":::"memory");
        __syncthreads();
        if(ks+2 < 64) load_stage((ks+2)%3, (ks+2)*32); else cpcommit();
        unsigned sb = smb + (unsigned)((ks%3)*SSTG*2);
#pragma unroll
        for(int kq=0;kq<2;kq++){
            unsigned ah[2][4], al[2][4], bh[4][4], bl[4][4];
#pragma unroll
            for(int mf=0;mf<2;mf++){
                ldsm4(ah[mf], sb + aoff[mf] + kq*32);
                ldsm4(al[mf], sb + (unsigned)(SMAT*2) + aoff[mf] + kq*32);
            }
#pragma unroll
            for(int jj=0;jj<4;jj++){
                ldsm4(bh[jj], sb + (unsigned)(2*SMAT*2) + boff[jj] + kq*32);
                ldsm4(bl[jj], sb + (unsigned)(3*SMAT*2) + boff[jj] + kq*32);
            }
#pragma unroll
            for(int mf=0;mf<2;mf++)
#pragma unroll
                for(int nf=0;nf<8;nf++){
                    const unsigned* bhf = &bh[nf>>1][(nf&1)*2];
                    const unsigned* blf = &bl[nf>>1][(nf&1)*2];
                    mma16816(acc[mf][nf], ah[mf], bhf);
                    mma16816(acc[mf][nf], ah[mf], blf);
                    mma16816(acc[mf][nf], al[mf], bhf);
                }
        }
    }

    const int r0 = bm + wm*32 + (lane>>2);
    if(Cf){
        const int c0 = bn + wn*64 + (lane&3)*2;
#pragma unroll
        for(int mf=0;mf<2;mf++)
#pragma unroll
            for(int nf=0;nf<8;nf++){
                float* p0 = Cf + (size_t)(r0 + mf*16)*2048 + c0 + nf*8;
                float* p1 = Cf + (size_t)(r0 + mf*16 + 8)*2048 + c0 + nf*8;
                *(float2*)p0 = make_float2(acc[mf][nf][0], acc[mf][nf][1]);
                *(float2*)p1 = make_float2(acc[mf][nf][2], acc[mf][nf][3]);
            }
    } else {
        __nv_bfloat16 *Oh, *Ol; int No, cbase; float scl;
        if(bn < 2048){ Oh=qh; Ol=ql; No=2048; scl=QSCALE; cbase=bn; }
        else if(bn < 2560){ Oh=kh; Ol=kl; No=512; scl=1.f; cbase=bn-2048; }
        else { Oh=vh; Ol=vl; No=512; scl=1.f; cbase=bn-2560; }
        const int c0 = cbase + wn*64 + (lane&3)*2;
#pragma unroll
        for(int mf=0;mf<2;mf++)
#pragma unroll
            for(int nf=0;nf<8;nf++)
#pragma unroll
                for(int hl=0;hl<2;hl++){
                    float v0 = acc[mf][nf][hl*2]*scl, v1 = acc[mf][nf][hl*2+1]*scl;
                    unsigned hh = packbf(v0, v1);
                    float h0 = __uint_as_float(hh<<16);
                    float h1 = __uint_as_float(hh & 0xffff0000u);
                    unsigned ll = packbf(v0-h0, v1-h1);
                    size_t idx = (size_t)(r0 + mf*16 + hl*8)*No + c0 + nf*8;
                    *(unsigned*)(Oh + idx) = hh;
                    *(unsigned*)(Ol + idx) = ll;
                }
    }
}

// ---------------------------------------------------------------------------
// mma.sync flash attention, KV tile = 128, no-max softmax.
// MMA issue order restructured for accumulator independence:
//   QK: ks outer / ng inner (16 accumulators cycled before reuse)
//   PV: ks outer / dg inner, exp+pack fused per-ks (8 accumulators cycled)
// ---------------------------------------------------------------------------
#define ASTR 72
#define A_QL (128*ASTR)
#define A_ST (2*A_QL)
#define A_MS (128*ASTR)
#define A_SS (4*A_MS)
#define ASMEM ((A_ST + 2*A_SS)*2)   // 184320 B

__global__ void __launch_bounds__(256,1)
attn_mma(const __nv_bfloat16* __restrict__ Qh_, const __nv_bfloat16* __restrict__ Ql_,
         const __nv_bfloat16* __restrict__ Kh_, const __nv_bfloat16* __restrict__ Kl_,
         const __nv_bfloat16* __restrict__ Vh_, const __nv_bfloat16* __restrict__ Vl_,
         __nv_bfloat16* __restrict__ Ch, __nv_bfloat16* __restrict__ Cl){
    extern __shared__ __nv_bfloat16 sm[];
    const unsigned smb = (unsigned)__cvta_generic_to_shared(sm);
    const int tid = threadIdx.x, lane = tid&31, wid = tid>>5;
    const int qt = blockIdx.x, bh = blockIdx.y;
    const int b = bh>>5, h = bh&31, kvh = h>>2;
    const int qbase = b*2048 + qt*128;
    const int kbase0 = b*2048;
    const int kvcol = kvh*64;
    const __nv_bfloat16* kvsrc[4] = {Kh_, Kl_, Vh_, Vl_};

    // Q tiles
#pragma unroll
    for(int t=0;t<8;t++){
        int c = tid + t*256;
        int mat = c >> 10, idx = c & 1023;
        int row = idx>>3, ch = idx&7;
        const __nv_bfloat16* src = (mat ? Ql_ : Qh_) + (size_t)(qbase+row)*2048 + h*64 + ch*8;
        unsigned dst = smb + (unsigned)((mat*A_QL + row*ASTR)*2 + ch*16);
        cpa16(dst, src);
    }
    cpcommit();

    auto load_kv = [&](int s, int kt){
#pragma unroll
        for(int t=0;t<16;t++){
            int c = tid + t*256;
            int mat = c>>10, idx = c&1023;
            int row = idx>>3, ch = idx&7;
            const __nv_bfloat16* src = kvsrc[mat] + (size_t)(kbase0 + kt*128 + row)*512 + kvcol + ch*8;
            unsigned dst = smb + (unsigned)((A_ST + s*A_SS + mat*A_MS + row*ASTR)*2 + ch*16);
            cpa16(dst, src);
        }
        cpcommit();
    };
    load_kv(0, 0);
    load_kv(1, 1);

    asm volatile("cp.async.wait_group 2;":::"memory");
    __syncthreads();

    unsigned aqh[4][4], aql[4][4];
    const unsigned qro = (unsigned)(((wid*16 + (lane&15))*ASTR)*2 + (lane>>4)*16);
#pragma unroll
    for(int ks=0;ks<4;ks++){
        ldsm4(aqh[ks], smb + qro + ks*32);
        ldsm4(aql[ks], smb + (unsigned)(A_QL*2) + qro + ks*32);
    }

    float od[8][4];
#pragma unroll
    for(int nf=0;nf<8;nf++)
#pragma unroll
        for(int q=0;q<4;q++) od[nf][q]=0.f;
    float l0=0.f, l1=0.f;

    const unsigned bro_col = (unsigned)(((lane>>3)&1)*16);
    const unsigned bro_row = (unsigned)((lane&7) + (lane>>4)*8);
    const unsigned tro_row = (unsigned)((lane&7) + ((lane>>3)&1)*8);
    const unsigned tro_col = (unsigned)((lane>>4)*16);

    for(int kt=0;kt<16;kt++){
        asm volatile("cp.async.wait_group 1;":::"memory");
        __syncthreads();
        unsigned sb = smb + (unsigned)((A_ST + (kt&1)*A_SS)*2);

        // ---- S = Q @ K^T : ks outer, ng inner (accumulator-independent) ----
        float sc[16][4];
#pragma unroll
        for(int nf=0;nf<16;nf++)
#pragma unroll
            for(int q=0;q<4;q++) sc[nf][q]=0.f;

#pragma unroll
        for(int ks=0;ks<4;ks++){
#pragma unroll
            for(int ng=0;ng<8;ng++){
                unsigned kh4[4], kl4[4];
                unsigned ro = (unsigned)((ng*16 + bro_row)*ASTR*2) + bro_col + ks*32;
                ldsm4(kh4, sb + ro);
                ldsm4(kl4, sb + (unsigned)(A_MS*2) + ro);
                // interleave hf streams: same-acc reuse distance = 2
                mma16816(sc[ng*2+0], aqh[ks], &kh4[0]);
                mma16816(sc[ng*2+1], aqh[ks], &kh4[2]);
                mma16816(sc[ng*2+0], aqh[ks], &kl4[0]);
                mma16816(sc[ng*2+1], aqh[ks], &kl4[2]);
                mma16816(sc[ng*2+0], aql[ks], &kh4[0]);
                mma16816(sc[ng*2+1], aql[ks], &kh4[2]);
            }
        }

        // ---- PV: per-ks exp2+pack fused, dg inner (8 accumulators cycled) ----
#pragma unroll
        for(int ks=0;ks<8;ks++){
            unsigned aph[4], apl[4];
#pragma unroll
            for(int q=0;q<4;q++){
                int nf = ks*2 + (q>>1);
                float v0 = ex2f(sc[nf][(q&1)*2]);
                float v1 = ex2f(sc[nf][(q&1)*2+1]);
                if(q&1) l1 += v0 + v1; else l0 += v0 + v1;
                unsigned hh = packbf(v0, v1);
                float h0 = __uint_as_float(hh<<16);
                float h1 = __uint_as_float(hh & 0xffff0000u);
                aph[q] = hh;
                apl[q] = packbf(v0-h0, v1-h1);
            }
#pragma unroll
            for(int dg=0;dg<4;dg++){
                unsigned vh4[4], vl4[4];
                unsigned ro = (unsigned)((ks*16 + tro_row)*ASTR*2) + dg*32 + tro_col;
                ldsm4t(vh4, sb + (unsigned)(2*A_MS*2) + ro);
                ldsm4t(vl4, sb + (unsigned)(3*A_MS*2) + ro);
                mma16816(od[dg*2+0], aph, &vh4[0]);
                mma16816(od[dg*2+1], aph, &vh4[2]);
                mma16816(od[dg*2+0], aph, &vl4[0]);
                mma16816(od[dg*2+1], aph, &vl4[2]);
                mma16816(od[dg*2+0], apl, &vh4[0]);
                mma16816(od[dg*2+1], apl, &vh4[2]);
            }
        }

        __syncthreads();
        if(kt+2 < 16) load_kv(kt&1, kt+2); else cpcommit();
    }

    // final l reduction + normalize + split-write ctx
    l0 += __shfl_xor_sync(0xffffffffu, l0, 1);
    l0 += __shfl_xor_sync(0xffffffffu, l0, 2);
    l1 += __shfl_xor_sync(0xffffffffu, l1, 1);
    l1 += __shfl_xor_sync(0xffffffffu, l1, 2);
    float inv0 = 1.f/l0, inv1 = 1.f/l1;
    const int r = lane>>2, cb = (lane&3)*2;
    size_t i0 = (size_t)(qbase + wid*16 + r)*2048 + h*64 + cb;
    size_t i1 = i0 + (size_t)8*2048;
#pragma unroll
    for(int nf=0;nf<8;nf++){
        float v0 = od[nf][0]*inv0, v1 = od[nf][1]*inv0;
        unsigned hh = packbf(v0, v1);
        float h0 = __uint_as_float(hh<<16), h1 = __uint_as_float(hh & 0xffff0000u);
        *(unsigned*)(Ch + i0 + nf*8) = hh;
        *(unsigned*)(Cl + i0 + nf*8) = packbf(v0-h0, v1-h1);
        float w0 = od[nf][2]*inv1, w1 = od[nf][3]*inv1;
        unsigned gg = packbf(w0, w1);
        float g0 = __uint_as_float(gg<<16), g1 = __uint_as_float(gg & 0xffff0000u);
        *(unsigned*)(Ch + i1 + nf*8) = gg;
        *(unsigned*)(Cl + i1 + nf*8) = packbf(w0-g0, w1-g1);
    }
}

extern "C" void kernel_launch(void* const* d_in, const int* in_sizes, int n_in,
                              void* d_out, int out_size){
    const float* x  = (const float*)d_in[0];
    const float* Wq = (const float*)d_in[1];
    const float* Wk = (const float*)d_in[2];
    const float* Wv = (const float*)d_in[3];
    const float* Wo = (const float*)d_in[4];
    float* out = (float*)d_out;

    void *xh,*xl,*wh,*wl,*woh,*wol,*qh,*ql,*kh,*kl,*vh,*vl;
    cudaGetSymbolAddress(&xh,g_xh);  cudaGetSymbolAddress(&xl,g_xl);
    cudaGetSymbolAddress(&wh,g_wqkvh); cudaGetSymbolAddress(&wl,g_wqkvl);
    cudaGetSymbolAddress(&woh,g_woh);cudaGetSymbolAddress(&wol,g_wol);
    cudaGetSymbolAddress(&qh,g_qh);  cudaGetSymbolAddress(&ql,g_ql);
    cudaGetSymbolAddress(&kh,g_kh);  cudaGetSymbolAddress(&kl,g_kl);
    cudaGetSymbolAddress(&vh,g_vh);  cudaGetSymbolAddress(&vl,g_vl);

    cudaFuncSetAttribute(gemm_mma, cudaFuncAttributeMaxDynamicSharedMemorySize, GSMEM);
    cudaFuncSetAttribute(attn_mma, cudaFuncAttributeMaxDynamicSharedMemorySize, ASMEM);

    wsplitAll<<<dim3(160,64),dim3(32,8)>>>(Wq, Wk, Wv, Wo,
        (__nv_bfloat16*)wh, (__nv_bfloat16*)wl, (__nv_bfloat16*)woh, (__nv_bfloat16*)wol);
    fsplit<<<512,256>>>((const float4*)x, (ull*)xh, (ull*)xl, 4096*2048/4, 1.0f);
    gemm_mma<<<dim3(24,32),256,GSMEM>>>((__nv_bfloat16*)xh,(__nv_bfloat16*)xl,
        (__nv_bfloat16*)wh,(__nv_bfloat16*)wl, nullptr,
        (__nv_bfloat16*)qh,(__nv_bfloat16*)ql,
        (__nv_bfloat16*)kh,(__nv_bfloat16*)kl,
        (__nv_bfloat16*)vh,(__nv_bfloat16*)vl);
    attn_mma<<<dim3(16,64),256,ASMEM>>>((__nv_bfloat16*)qh,(__nv_bfloat16*)ql,
        (__nv_bfloat16*)kh,(__nv_bfloat16*)kl,
        (__nv_bfloat16*)vh,(__nv_bfloat16*)vl,
        (__nv_bfloat16*)xh,(__nv_bfloat16*)xl);
    gemm_mma<<<dim3(16,32),256,GSMEM>>>((__nv_bfloat16*)xh,(__nv_bfloat16*)xl,
        (__nv_bfloat16*)woh,(__nv_bfloat16*)wol, out,
        nullptr,nullptr,nullptr,nullptr,nullptr,nullptr);
}

// round 12
// speedup vs baseline: 1.0025x; 1.0025x over previous
#include <cuda_runtime.h>
#include <cuda_bf16.h>
#include <math.h>

typedef unsigned long long ull;

// ---- scratch ----
__device__ __nv_bfloat16 g_xh[4096*2048], g_xl[4096*2048];   // x split; reused for ctx
__device__ __nv_bfloat16 g_wqkvh[3072*2048], g_wqkvl[3072*2048]; // concat WqT|WkT|WvT
__device__ __nv_bfloat16 g_woh[2048*2048], g_wol[2048*2048];
__device__ __nv_bfloat16 g_qh[4096*2048], g_ql[4096*2048];
__device__ __nv_bfloat16 g_kh[4096*512],  g_kl[4096*512];
__device__ __nv_bfloat16 g_vh[4096*512],  g_vl[4096*512];

#define QSCALE (0.125f * 1.4426950408889634f)   // 1/sqrt(64) * log2(e)

// fp32 -> hi/lo bf16 split
__global__ void __launch_bounds__(256) fsplit(const float4* __restrict__ in,
                                              ull* __restrict__ oh, ull* __restrict__ ol,
                                              int n4, float scale){
    int i = blockIdx.x*blockDim.x + threadIdx.x, st = gridDim.x*blockDim.x;
    for(; i < n4; i += st){
        float4 v = in[i]; float f[4] = {v.x*scale, v.y*scale, v.z*scale, v.w*scale};
        ull h=0,l=0;
#pragma unroll
        for(int j=0;j<4;j++){
            __nv_bfloat16 hb = __float2bfloat16(f[j]);
            __nv_bfloat16 lb = __float2bfloat16(f[j]-__bfloat162float(hb));
            h |= (ull)__bfloat16_as_ushort(hb) << (16*j);
            l |= (ull)__bfloat16_as_ushort(lb) << (16*j);
        }
        oh[i]=h; ol[i]=l;
    }
}

// all 4 weight transposed-splits in one launch
__global__ void wsplitAll(const float* __restrict__ Wq, const float* __restrict__ Wk,
                          const float* __restrict__ Wv, const float* __restrict__ Wo,
                          __nv_bfloat16* __restrict__ qkvh, __nv_bfloat16* __restrict__ qkvl,
                          __nv_bfloat16* __restrict__ woh, __nv_bfloat16* __restrict__ wol){
    __shared__ float t[32][33];
    int bx = blockIdx.x;
    const float* W; __nv_bfloat16 *Th, *Tl; int N, n0;
    if(bx < 64){ W=Wq; Th=qkvh; Tl=qkvl; N=2048; n0=bx*32; }
    else if(bx < 80){ W=Wk; Th=qkvh+(size_t)2048*2048; Tl=qkvl+(size_t)2048*2048; N=512; n0=(bx-64)*32; }
    else if(bx < 96){ W=Wv; Th=qkvh+(size_t)2560*2048; Tl=qkvl+(size_t)2560*2048; N=512; n0=(bx-80)*32; }
    else { W=Wo; Th=woh; Tl=wol; N=2048; n0=(bx-96)*32; }
    int k0 = blockIdx.y*32;
    int tx = threadIdx.x, ty = threadIdx.y;
#pragma unroll
    for(int p=0;p<32;p+=8) t[ty+p][tx] = W[(size_t)(k0+ty+p)*N + n0+tx];
    __syncthreads();
#pragma unroll
    for(int p=0;p<32;p+=8){
        float v = t[tx][ty+p];
        __nv_bfloat16 h = __float2bfloat16(v);
        __nv_bfloat16 l = __float2bfloat16(v-__bfloat162float(h));
        Th[(size_t)(n0+ty+p)*2048 + k0+tx] = h;
        Tl[(size_t)(n0+ty+p)*2048 + k0+tx] = l;
    }
}

// ---- mma helpers ----
__device__ __forceinline__ void ldsm4(unsigned* r, unsigned a){
    asm volatile("ldmatrix.sync.aligned.m8n8.x4.shared.b16 {%0,%1,%2,%3},[%4];"
                 :"=r"(r[0]),"=r"(r[1]),"=r"(r[2]),"=r"(r[3]):"r"(a));
}
__device__ __forceinline__ void ldsm4t(unsigned* r, unsigned a){
    asm volatile("ldmatrix.sync.aligned.m8n8.x4.trans.shared.b16 {%0,%1,%2,%3},[%4];"
                 :"=r"(r[0]),"=r"(r[1]),"=r"(r[2]),"=r"(r[3]):"r"(a));
}
__device__ __forceinline__ void mma16816(float* c, const unsigned* a, const unsigned* b){
    asm volatile("mma.sync.aligned.m16n8k16.row.col.f32.bf16.bf16.f32 "
                 "{%0,%1,%2,%3},{%4,%5,%6,%7},{%8,%9},{%0,%1,%2,%3};"
                 :"+f"(c[0]),"+f"(c[1]),"+f"(c[2]),"+f"(c[3])
                 :"r"(a[0]),"r"(a[1]),"r"(a[2]),"r"(a[3]),"r"(b[0]),"r"(b[1]));
}
__device__ __forceinline__ void cpa16(unsigned d, const void* s){
    asm volatile("cp.async.cg.shared.global [%0],[%1],16;"::"r"(d),"l"(s):"memory");
}
__device__ __forceinline__ void cpcommit(){ asm volatile("cp.async.commit_group;":::"memory"); }
__device__ __forceinline__ unsigned packbf(float lo, float hi){
    unsigned r; asm("cvt.rn.bf16x2.f32 %0, %1, %2;":"=r"(r):"f"(hi),"f"(lo)); return r;
}
__device__ __forceinline__ float ex2f(float x){
    float r; asm("ex2.approx.ftz.f32 %0,%1;":"=f"(r):"f"(x)); return r;
}

// ---------------------------------------------------------------------------
// mma.sync GEMM (verified, unchanged)
// ---------------------------------------------------------------------------
#define SROW 40
#define SMAT (128*SROW)
#define SSTG (4*SMAT)
#define GSMEM (3*SSTG*2)

__global__ void __launch_bounds__(256,1)
gemm_mma(const __nv_bfloat16* __restrict__ Ah, const __nv_bfloat16* __restrict__ Al,
         const __nv_bfloat16* __restrict__ Bh, const __nv_bfloat16* __restrict__ Bl,
         float* __restrict__ Cf,
         __nv_bfloat16* __restrict__ qh, __nv_bfloat16* __restrict__ ql,
         __nv_bfloat16* __restrict__ kh, __nv_bfloat16* __restrict__ kl,
         __nv_bfloat16* __restrict__ vh, __nv_bfloat16* __restrict__ vl){
    extern __shared__ __nv_bfloat16 sm[];
    const unsigned smb = (unsigned)__cvta_generic_to_shared(sm);
    const int tid = threadIdx.x, lane = tid & 31, wid = tid >> 5;
    const int wm = wid >> 1, wn = wid & 1;
    const int bm = blockIdx.y * 128, bn = blockIdx.x * 128;
    const __nv_bfloat16* gsrc[4] = {Ah, Al, Bh, Bl};

    float acc[2][8][4];
#pragma unroll
    for(int i=0;i<2;i++)
#pragma unroll
        for(int j=0;j<8;j++)
#pragma unroll
            for(int q=0;q<4;q++) acc[i][j][q]=0.f;

    unsigned aoff[2], boff[4];
#pragma unroll
    for(int mf=0;mf<2;mf++)
        aoff[mf] = (unsigned)((wm*32 + mf*16 + (lane&7) + ((lane>>3)&1)*8)*(SROW*2) + (lane>>4)*16);
#pragma unroll
    for(int jj=0;jj<4;jj++)
        boff[jj] = (unsigned)((wn*64 + jj*16 + (lane&7) + (lane>>4)*8)*(SROW*2) + ((lane>>3)&1)*16);

    auto load_stage = [&](int s, int k0){
#pragma unroll
        for(int t=0;t<8;t++){
            int c = tid + t*256;
            int g = c >> 9;
            int idx = c & 511;
            int row = idx >> 2, kc = idx & 3;
            int grow = (g < 2 ? bm : bn) + row;
            const __nv_bfloat16* src = gsrc[g] + (size_t)grow*2048 + k0 + kc*8;
            unsigned dst = smb + (unsigned)((s*SSTG + g*SMAT + row*SROW)*2 + kc*16);
            cpa16(dst, src);
        }
        cpcommit();
    };

    load_stage(0, 0);
    load_stage(1, 32);

    for(int ks=0; ks<64; ks++){
        asm volatile("cp.async.wait_group 1;":::"memory");
        __syncthreads();
        if(ks+2 < 64) load_stage((ks+2)%3, (ks+2)*32); else cpcommit();
        unsigned sb = smb + (unsigned)((ks%3)*SSTG*2);
#pragma unroll
        for(int kq=0;kq<2;kq++){
            unsigned ah[2][4], al[2][4], bh[4][4], bl[4][4];
#pragma unroll
            for(int mf=0;mf<2;mf++){
                ldsm4(ah[mf], sb + aoff[mf] + kq*32);
                ldsm4(al[mf], sb + (unsigned)(SMAT*2) + aoff[mf] + kq*32);
            }
#pragma unroll
            for(int jj=0;jj<4;jj++){
                ldsm4(bh[jj], sb + (unsigned)(2*SMAT*2) + boff[jj] + kq*32);
                ldsm4(bl[jj], sb + (unsigned)(3*SMAT*2) + boff[jj] + kq*32);
            }
#pragma unroll
            for(int mf=0;mf<2;mf++)
#pragma unroll
                for(int nf=0;nf<8;nf++){
                    const unsigned* bhf = &bh[nf>>1][(nf&1)*2];
                    const unsigned* blf = &bl[nf>>1][(nf&1)*2];
                    mma16816(acc[mf][nf], ah[mf], bhf);
                    mma16816(acc[mf][nf], ah[mf], blf);
                    mma16816(acc[mf][nf], al[mf], bhf);
                }
        }
    }

    const int r0 = bm + wm*32 + (lane>>2);
    if(Cf){
        const int c0 = bn + wn*64 + (lane&3)*2;
#pragma unroll
        for(int mf=0;mf<2;mf++)
#pragma unroll
            for(int nf=0;nf<8;nf++){
                float* p0 = Cf + (size_t)(r0 + mf*16)*2048 + c0 + nf*8;
                float* p1 = Cf + (size_t)(r0 + mf*16 + 8)*2048 + c0 + nf*8;
                *(float2*)p0 = make_float2(acc[mf][nf][0], acc[mf][nf][1]);
                *(float2*)p1 = make_float2(acc[mf][nf][2], acc[mf][nf][3]);
            }
    } else {
        __nv_bfloat16 *Oh, *Ol; int No, cbase; float scl;
        if(bn < 2048){ Oh=qh; Ol=ql; No=2048; scl=QSCALE; cbase=bn; }
        else if(bn < 2560){ Oh=kh; Ol=kl; No=512; scl=1.f; cbase=bn-2048; }
        else { Oh=vh; Ol=vl; No=512; scl=1.f; cbase=bn-2560; }
        const int c0 = cbase + wn*64 + (lane&3)*2;
#pragma unroll
        for(int mf=0;mf<2;mf++)
#pragma unroll
            for(int nf=0;nf<8;nf++)
#pragma unroll
                for(int hl=0;hl<2;hl++){
                    float v0 = acc[mf][nf][hl*2]*scl, v1 = acc[mf][nf][hl*2+1]*scl;
                    unsigned hh = packbf(v0, v1);
                    float h0 = __uint_as_float(hh<<16);
                    float h1 = __uint_as_float(hh & 0xffff0000u);
                    unsigned ll = packbf(v0-h0, v1-h1);
                    size_t idx = (size_t)(r0 + mf*16 + hl*8)*No + c0 + nf*8;
                    *(unsigned*)(Oh + idx) = hh;
                    *(unsigned*)(Ol + idx) = ll;
                }
    }
}

// ---------------------------------------------------------------------------
// mma.sync flash attention: 128 threads (4 warps), q-tile 64, kv-tile 64,
// 2-stage, 92KB smem -> 2 CTAs/SM. Independent CTAs desynchronize the
// softmax phase so the SM's tensor pipe stays fed.
// ---------------------------------------------------------------------------
#define ASTR 72
#define A_QL (64*ASTR)
#define A_ST (2*A_QL)
#define A_MS (64*ASTR)
#define A_SS (4*A_MS)
#define ASMEM ((A_ST + 2*A_SS)*2)   // 92160 B

__global__ void __launch_bounds__(128,2)
attn_mma(const __nv_bfloat16* __restrict__ Qh_, const __nv_bfloat16* __restrict__ Ql_,
         const __nv_bfloat16* __restrict__ Kh_, const __nv_bfloat16* __restrict__ Kl_,
         const __nv_bfloat16* __restrict__ Vh_, const __nv_bfloat16* __restrict__ Vl_,
         __nv_bfloat16* __restrict__ Ch, __nv_bfloat16* __restrict__ Cl){
    extern __shared__ __nv_bfloat16 sm[];
    const unsigned smb = (unsigned)__cvta_generic_to_shared(sm);
    const int tid = threadIdx.x, lane = tid&31, wid = tid>>5;
    const int qt = blockIdx.x, bh = blockIdx.y;
    const int b = bh>>5, h = bh&31, kvh = h>>2;
    const int qbase = b*2048 + qt*64;
    const int kbase0 = b*2048;
    const int kvcol = kvh*64;
    const __nv_bfloat16* kvsrc[4] = {Kh_, Kl_, Vh_, Vl_};

    // Q tiles (hi,lo): 2 x 64 rows x 64 cols = 1024 16B-chunks / 128 thr = 8 iters
#pragma unroll
    for(int t=0;t<8;t++){
        int c = tid + t*128;
        int mat = c >> 9, idx = c & 511;
        int row = idx>>3, ch = idx&7;
        const __nv_bfloat16* src = (mat ? Ql_ : Qh_) + (size_t)(qbase+row)*2048 + h*64 + ch*8;
        unsigned dst = smb + (unsigned)((mat*A_QL + row*ASTR)*2 + ch*16);
        cpa16(dst, src);
    }
    cpcommit();

    // KV stage: 4 mats x 64 rows x 8 chunks = 2048 / 128 = 16 iters
    auto load_kv = [&](int s, int kt){
#pragma unroll
        for(int t=0;t<16;t++){
            int c = tid + t*128;
            int mat = c>>9, idx = c&511;
            int row = idx>>3, ch = idx&7;
            const __nv_bfloat16* src = kvsrc[mat] + (size_t)(kbase0 + kt*64 + row)*512 + kvcol + ch*8;
            unsigned dst = smb + (unsigned)((A_ST + s*A_SS + mat*A_MS + row*ASTR)*2 + ch*16);
            cpa16(dst, src);
        }
        cpcommit();
    };
    load_kv(0, 0);
    load_kv(1, 1);

    asm volatile("cp.async.wait_group 2;":::"memory");
    __syncthreads();

    unsigned aqh[4][4], aql[4][4];
    const unsigned qro = (unsigned)(((wid*16 + (lane&15))*ASTR)*2 + (lane>>4)*16);
#pragma unroll
    for(int ks=0;ks<4;ks++){
        ldsm4(aqh[ks], smb + qro + ks*32);
        ldsm4(aql[ks], smb + (unsigned)(A_QL*2) + qro + ks*32);
    }

    float od[8][4];
#pragma unroll
    for(int nf=0;nf<8;nf++)
#pragma unroll
        for(int q=0;q<4;q++) od[nf][q]=0.f;
    float l0=0.f, l1=0.f;

    const unsigned bro_col = (unsigned)(((lane>>3)&1)*16);
    const unsigned bro_row = (unsigned)((lane&7) + (lane>>4)*8);
    const unsigned tro_row = (unsigned)((lane&7) + ((lane>>3)&1)*8);
    const unsigned tro_col = (unsigned)((lane>>4)*16);

    for(int kt=0;kt<32;kt++){
        asm volatile("cp.async.wait_group 1;":::"memory");
        __syncthreads();
        unsigned sb = smb + (unsigned)((A_ST + (kt&1)*A_SS)*2);

        // ---- S = Q @ K^T : 64q x 64k -> sc[8][4] ----
        float sc[8][4];
#pragma unroll
        for(int nf=0;nf<8;nf++)
#pragma unroll
            for(int q=0;q<4;q++) sc[nf][q]=0.f;

#pragma unroll
        for(int ks=0;ks<4;ks++){
#pragma unroll
            for(int ng=0;ng<4;ng++){
                unsigned kh4[4], kl4[4];
                unsigned ro = (unsigned)((ng*16 + bro_row)*ASTR*2) + bro_col + ks*32;
                ldsm4(kh4, sb + ro);
                ldsm4(kl4, sb + (unsigned)(A_MS*2) + ro);
                mma16816(sc[ng*2+0], aqh[ks], &kh4[0]);
                mma16816(sc[ng*2+1], aqh[ks], &kh4[2]);
                mma16816(sc[ng*2+0], aqh[ks], &kl4[0]);
                mma16816(sc[ng*2+1], aqh[ks], &kl4[2]);
                mma16816(sc[ng*2+0], aql[ks], &kh4[0]);
                mma16816(sc[ng*2+1], aql[ks], &kh4[2]);
            }
        }

        // ---- PV: per-ks exp2+pack fused, dg inner ----
#pragma unroll
        for(int ks=0;ks<4;ks++){
            unsigned aph[4], apl[4];
#pragma unroll
            for(int q=0;q<4;q++){
                int nf = ks*2 + (q>>1);
                float v0 = ex2f(sc[nf][(q&1)*2]);
                float v1 = ex2f(sc[nf][(q&1)*2+1]);
                if(q&1) l1 += v0 + v1; else l0 += v0 + v1;
                unsigned hh = packbf(v0, v1);
                float h0 = __uint_as_float(hh<<16);
                float h1 = __uint_as_float(hh & 0xffff0000u);
                aph[q] = hh;
                apl[q] = packbf(v0-h0, v1-h1);
            }
#pragma unroll
            for(int dg=0;dg<4;dg++){
                unsigned vh4[4], vl4[4];
                unsigned ro = (unsigned)((ks*16 + tro_row)*ASTR*2) + dg*32 + tro_col;
                ldsm4t(vh4, sb + (unsigned)(2*A_MS*2) + ro);
                ldsm4t(vl4, sb + (unsigned)(3*A_MS*2) + ro);
                mma16816(od[dg*2+0], aph, &vh4[0]);
                mma16816(od[dg*2+1], aph, &vh4[2]);
                mma16816(od[dg*2+0], aph, &vl4[0]);
                mma16816(od[dg*2+1], aph, &vl4[2]);
                mma16816(od[dg*2+0], apl, &vh4[0]);
                mma16816(od[dg*2+1], apl, &vh4[2]);
            }
        }

        __syncthreads();
        if(kt+2 < 32) load_kv(kt&1, kt+2); else cpcommit();
    }

    // final l reduction + normalize + split-write ctx
    l0 += __shfl_xor_sync(0xffffffffu, l0, 1);
    l0 += __shfl_xor_sync(0xffffffffu, l0, 2);
    l1 += __shfl_xor_sync(0xffffffffu, l1, 1);
    l1 += __shfl_xor_sync(0xffffffffu, l1, 2);
    float inv0 = 1.f/l0, inv1 = 1.f/l1;
    const int r = lane>>2, cb = (lane&3)*2;
    size_t i0 = (size_t)(qbase + wid*16 + r)*2048 + h*64 + cb;
    size_t i1 = i0 + (size_t)8*2048;
#pragma unroll
    for(int nf=0;nf<8;nf++){
        float v0 = od[nf][0]*inv0, v1 = od[nf][1]*inv0;
        unsigned hh = packbf(v0, v1);
        float h0 = __uint_as_float(hh<<16), h1 = __uint_as_float(hh & 0xffff0000u);
        *(unsigned*)(Ch + i0 + nf*8) = hh;
        *(unsigned*)(Cl + i0 + nf*8) = packbf(v0-h0, v1-h1);
        float w0 = od[nf][2]*inv1, w1 = od[nf][3]*inv1;
        unsigned gg = packbf(w0, w1);
        float g0 = __uint_as_float(gg<<16), g1 = __uint_as_float(gg & 0xffff0000u);
        *(unsigned*)(Ch + i1 + nf*8) = gg;
        *(unsigned*)(Cl + i1 + nf*8) = packbf(w0-g0, w1-g1);
    }
}

extern "C" void kernel_launch(void* const* d_in, const int* in_sizes, int n_in,
                              void* d_out, int out_size){
    const float* x  = (const float*)d_in[0];
    const float* Wq = (const float*)d_in[1];
    const float* Wk = (const float*)d_in[2];
    const float* Wv = (const float*)d_in[3];
    const float* Wo = (const float*)d_in[4];
    float* out = (float*)d_out;

    void *xh,*xl,*wh,*wl,*woh,*wol,*qh,*ql,*kh,*kl,*vh,*vl;
    cudaGetSymbolAddress(&xh,g_xh);  cudaGetSymbolAddress(&xl,g_xl);
    cudaGetSymbolAddress(&wh,g_wqkvh); cudaGetSymbolAddress(&wl,g_wqkvl);
    cudaGetSymbolAddress(&woh,g_woh);cudaGetSymbolAddress(&wol,g_wol);
    cudaGetSymbolAddress(&qh,g_qh);  cudaGetSymbolAddress(&ql,g_ql);
    cudaGetSymbolAddress(&kh,g_kh);  cudaGetSymbolAddress(&kl,g_kl);
    cudaGetSymbolAddress(&vh,g_vh);  cudaGetSymbolAddress(&vl,g_vl);

    cudaFuncSetAttribute(gemm_mma, cudaFuncAttributeMaxDynamicSharedMemorySize, GSMEM);
    cudaFuncSetAttribute(attn_mma, cudaFuncAttributeMaxDynamicSharedMemorySize, ASMEM);

    wsplitAll<<<dim3(160,64),dim3(32,8)>>>(Wq, Wk, Wv, Wo,
        (__nv_bfloat16*)wh, (__nv_bfloat16*)wl, (__nv_bfloat16*)woh, (__nv_bfloat16*)wol);
    fsplit<<<512,256>>>((const float4*)x, (ull*)xh, (ull*)xl, 4096*2048/4, 1.0f);
    gemm_mma<<<dim3(24,32),256,GSMEM>>>((__nv_bfloat16*)xh,(__nv_bfloat16*)xl,
        (__nv_bfloat16*)wh,(__nv_bfloat16*)wl, nullptr,
        (__nv_bfloat16*)qh,(__nv_bfloat16*)ql,
        (__nv_bfloat16*)kh,(__nv_bfloat16*)kl,
        (__nv_bfloat16*)vh,(__nv_bfloat16*)vl);
    attn_mma<<<dim3(32,64),128,ASMEM>>>((__nv_bfloat16*)qh,(__nv_bfloat16*)ql,
        (__nv_bfloat16*)kh,(__nv_bfloat16*)kl,
        (__nv_bfloat16*)vh,(__nv_bfloat16*)vl,
        (__nv_bfloat16*)xh,(__nv_bfloat16*)xl);
    gemm_mma<<<dim3(16,32),256,GSMEM>>>((__nv_bfloat16*)xh,(__nv_bfloat16*)xl,
        (__nv_bfloat16*)woh,(__nv_bfloat16*)wol, out,
        nullptr,nullptr,nullptr,nullptr,nullptr,nullptr);
}

// round 13
// speedup vs baseline: 1.2822x; 1.2790x over previous
#include <cuda_runtime.h>
#include <cuda.h>
#include <cuda_bf16.h>
#include <math.h>

typedef unsigned long long ull;

// ---- scratch ----
__device__ __nv_bfloat16 g_xh[4096*2048], g_xl[4096*2048];   // x split; reused for ctx
__device__ __nv_bfloat16 g_wqkvh[3072*2048], g_wqkvl[3072*2048]; // concat WqT|WkT|WvT
__device__ __nv_bfloat16 g_woh[2048*2048], g_wol[2048*2048];
__device__ __nv_bfloat16 g_qh[4096*2048], g_ql[4096*2048];
__device__ __nv_bfloat16 g_kh[4096*512],  g_kl[4096*512];
__device__ __nv_bfloat16 g_vh[4096*512],  g_vl[4096*512];

#define QSCALE (0.125f * 1.4426950408889634f)   // 1/sqrt(64) * log2(e)

// fp32 -> hi/lo bf16 split
__global__ void __launch_bounds__(256) fsplit(const float4* __restrict__ in,
                                              ull* __restrict__ oh, ull* __restrict__ ol,
                                              int n4, float scale){
    int i = blockIdx.x*blockDim.x + threadIdx.x, st = gridDim.x*blockDim.x;
    for(; i < n4; i += st){
        float4 v = in[i]; float f[4] = {v.x*scale, v.y*scale, v.z*scale, v.w*scale};
        ull h=0,l=0;
#pragma unroll
        for(int j=0;j<4;j++){
            __nv_bfloat16 hb = __float2bfloat16(f[j]);
            __nv_bfloat16 lb = __float2bfloat16(f[j]-__bfloat162float(hb));
            h |= (ull)__bfloat16_as_ushort(hb) << (16*j);
            l |= (ull)__bfloat16_as_ushort(lb) << (16*j);
        }
        oh[i]=h; ol[i]=l;
    }
}

// all 4 weight transposed-splits in one launch
__global__ void wsplitAll(const float* __restrict__ Wq, const float* __restrict__ Wk,
                          const float* __restrict__ Wv, const float* __restrict__ Wo,
                          __nv_bfloat16* __restrict__ qkvh, __nv_bfloat16* __restrict__ qkvl,
                          __nv_bfloat16* __restrict__ woh, __nv_bfloat16* __restrict__ wol){
    __shared__ float t[32][33];
    int bx = blockIdx.x;
    const float* W; __nv_bfloat16 *Th, *Tl; int N, n0;
    if(bx < 64){ W=Wq; Th=qkvh; Tl=qkvl; N=2048; n0=bx*32; }
    else if(bx < 80){ W=Wk; Th=qkvh+(size_t)2048*2048; Tl=qkvl+(size_t)2048*2048; N=512; n0=(bx-64)*32; }
    else if(bx < 96){ W=Wv; Th=qkvh+(size_t)2560*2048; Tl=qkvl+(size_t)2560*2048; N=512; n0=(bx-80)*32; }
    else { W=Wo; Th=woh; Tl=wol; N=2048; n0=(bx-96)*32; }
    int k0 = blockIdx.y*32;
    int tx = threadIdx.x, ty = threadIdx.y;
#pragma unroll
    for(int p=0;p<32;p+=8) t[ty+p][tx] = W[(size_t)(k0+ty+p)*N + n0+tx];
    __syncthreads();
#pragma unroll
    for(int p=0;p<32;p+=8){
        float v = t[tx][ty+p];
        __nv_bfloat16 h = __float2bfloat16(v);
        __nv_bfloat16 l = __float2bfloat16(v-__bfloat162float(h));
        Th[(size_t)(n0+ty+p)*2048 + k0+tx] = h;
        Tl[(size_t)(n0+ty+p)*2048 + k0+tx] = l;
    }
}

// ---- helpers ----
__device__ __forceinline__ void ldsm4(unsigned* r, unsigned a){
    asm volatile("ldmatrix.sync.aligned.m8n8.x4.shared.b16 {%0,%1,%2,%3},[%4];"
                 :"=r"(r[0]),"=r"(r[1]),"=r"(r[2]),"=r"(r[3]):"r"(a));
}
__device__ __forceinline__ void ldsm4t(unsigned* r, unsigned a){
    asm volatile("ldmatrix.sync.aligned.m8n8.x4.trans.shared.b16 {%0,%1,%2,%3},[%4];"
                 :"=r"(r[0]),"=r"(r[1]),"=r"(r[2]),"=r"(r[3]):"r"(a));
}
__device__ __forceinline__ void mma16816(float* c, const unsigned* a, const unsigned* b){
    asm volatile("mma.sync.aligned.m16n8k16.row.col.f32.bf16.bf16.f32 "
                 "{%0,%1,%2,%3},{%4,%5,%6,%7},{%8,%9},{%0,%1,%2,%3};"
                 :"+f"(c[0]),"+f"(c[1]),"+f"(c[2]),"+f"(c[3])
                 :"r"(a[0]),"r"(a[1]),"r"(a[2]),"r"(a[3]),"r"(b[0]),"r"(b[1]));
}
__device__ __forceinline__ void cpa16(unsigned d, const void* s){
    asm volatile("cp.async.cg.shared.global [%0],[%1],16;"::"r"(d),"l"(s):"memory");
}
__device__ __forceinline__ void cpcommit(){ asm volatile("cp.async.commit_group;":::"memory"); }
__device__ __forceinline__ unsigned packbf(float lo, float hi){
    unsigned r; asm("cvt.rn.bf16x2.f32 %0, %1, %2;":"=r"(r):"f"(hi),"f"(lo)); return r;
}
__device__ __forceinline__ float ex2f(float x){
    float r; asm("ex2.approx.ftz.f32 %0,%1;":"=f"(r):"f"(x)); return r;
}
__device__ __forceinline__ void mbar_init(unsigned a,unsigned c){
    asm volatile("mbarrier.init.shared.b64 [%0],%1;"::"r"(a),"r"(c):"memory");
}
__device__ __forceinline__ void mbar_expect(unsigned a,unsigned b){
    asm volatile("mbarrier.arrive.expect_tx.shared.b64 _,[%0],%1;"::"r"(a),"r"(b):"memory");
}
__device__ __forceinline__ void mbar_wait(unsigned a,unsigned p){
    asm volatile("{\n\t.reg .pred P;\nW_%=:\n\t"
                 "mbarrier.try_wait.parity.acquire.cta.shared::cta.b64 P,[%0],%1;\n\t"
                 "@!P bra W_%=;\n\t}"::"r"(a),"r"(p):"memory");
}
__device__ __forceinline__ void tma2(unsigned s,const CUtensorMap* m,int cx,int cy,unsigned mb){
    asm volatile("cp.async.bulk.tensor.2d.shared::cta.global.tile.mbarrier::complete_tx::bytes "
                 "[%0],[%1,{%2,%3}],[%4];"
                 ::"r"(s),"l"(m),"r"(cx),"r"(cy),"r"(mb):"memory");
}

// ---------------------------------------------------------------------------
// TMA-fed mma.sync GEMM: C = A[M][2048] @ B[N][2048]^T, bf16x3 split.
// CTA 128x128, K-chunk 64 (4 k16 steps), 2 stages x 64KB, SW128 swizzle.
// ldsm addr: phys = r*128 + (c ^ ((r&7)<<4)).
// ---------------------------------------------------------------------------
#define GSMEM (1024 + 2*65536)

__global__ void __launch_bounds__(256,1)
gemm_tma(const __grid_constant__ CUtensorMap tAh, const __grid_constant__ CUtensorMap tAl,
         const __grid_constant__ CUtensorMap tBh, const __grid_constant__ CUtensorMap tBl,
         float* __restrict__ Cf,
         __nv_bfloat16* __restrict__ qh, __nv_bfloat16* __restrict__ ql,
         __nv_bfloat16* __restrict__ kh, __nv_bfloat16* __restrict__ kl,
         __nv_bfloat16* __restrict__ vh, __nv_bfloat16* __restrict__ vl){
    extern __shared__ char smraw[];
    unsigned smu; asm("{ .reg .u64 t; cvta.to.shared.u64 t,%1; cvt.u32.u64 %0,t; }":"=r"(smu):"l"(smraw));
    const unsigned base = (smu + 1023u) & ~1023u;
    const unsigned mb0 = base, mb1 = base + 8;
    const unsigned tiles = base + 1024;
    const int tid = threadIdx.x, lane = tid & 31, wid = tid >> 5;
    const int wm = wid >> 1, wn = wid & 1;
    const int bm = blockIdx.y * 128, bn = blockIdx.x * 128;

    if(tid==0){ mbar_init(mb0,1); mbar_init(mb1,1); }
    __syncthreads();

    auto issue = [&](int s, int k0){
        unsigned mb = s ? mb1 : mb0;
        mbar_expect(mb, 65536u);
        unsigned dst = tiles + (unsigned)s*65536u;
        tma2(dst,          &tAh, k0, bm, mb);
        tma2(dst + 16384u, &tAl, k0, bm, mb);
        tma2(dst + 32768u, &tBh, k0, bn, mb);
        tma2(dst + 49152u, &tBl, k0, bn, mb);
    };
    if(tid==0){ issue(0, 0); issue(1, 64); }

    float acc[2][8][4];
#pragma unroll
    for(int i=0;i<2;i++)
#pragma unroll
        for(int j=0;j<8;j++)
#pragma unroll
            for(int q=0;q<4;q++) acc[i][j][q]=0.f;

    // per-lane base offsets (dense 128B rows + SW128 xor)
    unsigned arow[2], axor[2], brow[4], bxor[4];
#pragma unroll
    for(int mf=0;mf<2;mf++){
        int r = wm*32 + mf*16 + (lane&7) + ((lane>>3)&1)*8;
        arow[mf] = (unsigned)(r*128); axor[mf] = (unsigned)((r&7)<<4);
    }
#pragma unroll
    for(int jj=0;jj<4;jj++){
        int r = wn*64 + jj*16 + (lane&7) + (lane>>4)*8;
        brow[jj] = (unsigned)(r*128); bxor[jj] = (unsigned)((r&7)<<4);
    }
    const unsigned acol = (unsigned)((lane>>4)*16);
    const unsigned bcol = (unsigned)(((lane>>3)&1)*16);

    int ph[2] = {0,0};
    for(int it=0; it<32; ++it){
        int s = it & 1;
        mbar_wait(s?mb1:mb0, ph[s]); ph[s] ^= 1;
        unsigned sb = tiles + (unsigned)s*65536u;
#pragma unroll
        for(int ks=0;ks<4;ks++){
            unsigned ah[2][4], al[2][4], bh[4][4], bl[4][4];
#pragma unroll
            for(int mf=0;mf<2;mf++){
                unsigned c = (acol + ks*32);
                ldsm4(ah[mf], sb + arow[mf] + (c ^ axor[mf]));
                ldsm4(al[mf], sb + 16384u + arow[mf] + (c ^ axor[mf]));
            }
#pragma unroll
            for(int jj=0;jj<4;jj++){
                unsigned c = (bcol + ks*32);
                ldsm4(bh[jj], sb + 32768u + brow[jj] + (c ^ bxor[jj]));
                ldsm4(bl[jj], sb + 49152u + brow[jj] + (c ^ bxor[jj]));
            }
#pragma unroll
            for(int mf=0;mf<2;mf++)
#pragma unroll
                for(int nf=0;nf<8;nf++){
                    const unsigned* bhf = &bh[nf>>1][(nf&1)*2];
                    const unsigned* blf = &bl[nf>>1][(nf&1)*2];
                    mma16816(acc[mf][nf], ah[mf], bhf);
                    mma16816(acc[mf][nf], ah[mf], blf);
                    mma16816(acc[mf][nf], al[mf], bhf);
                }
        }
        __syncthreads();           // all warps done with stage s
        if(it+2 < 32 && tid==0) issue(s, (it+2)*64);
    }

    const int r0 = bm + wm*32 + (lane>>2);
    if(Cf){
        const int c0 = bn + wn*64 + (lane&3)*2;
#pragma unroll
        for(int mf=0;mf<2;mf++)
#pragma unroll
            for(int nf=0;nf<8;nf++){
                float* p0 = Cf + (size_t)(r0 + mf*16)*2048 + c0 + nf*8;
                float* p1 = Cf + (size_t)(r0 + mf*16 + 8)*2048 + c0 + nf*8;
                *(float2*)p0 = make_float2(acc[mf][nf][0], acc[mf][nf][1]);
                *(float2*)p1 = make_float2(acc[mf][nf][2], acc[mf][nf][3]);
            }
    } else {
        __nv_bfloat16 *Oh, *Ol; int No, cbase; float scl;
        if(bn < 2048){ Oh=qh; Ol=ql; No=2048; scl=QSCALE; cbase=bn; }
        else if(bn < 2560){ Oh=kh; Ol=kl; No=512; scl=1.f; cbase=bn-2048; }
        else { Oh=vh; Ol=vl; No=512; scl=1.f; cbase=bn-2560; }
        const int c0 = cbase + wn*64 + (lane&3)*2;
#pragma unroll
        for(int mf=0;mf<2;mf++)
#pragma unroll
            for(int nf=0;nf<8;nf++)
#pragma unroll
                for(int hl=0;hl<2;hl++){
                    float v0 = acc[mf][nf][hl*2]*scl, v1 = acc[mf][nf][hl*2+1]*scl;
                    unsigned hh = packbf(v0, v1);
                    float h0 = __uint_as_float(hh<<16);
                    float h1 = __uint_as_float(hh & 0xffff0000u);
                    unsigned ll = packbf(v0-h0, v1-h1);
                    size_t idx = (size_t)(r0 + mf*16 + hl*8)*No + c0 + nf*8;
                    *(unsigned*)(Oh + idx) = hh;
                    *(unsigned*)(Ol + idx) = ll;
                }
    }
}

// ---------------------------------------------------------------------------
// mma.sync flash attention (verified round 12, unchanged)
// ---------------------------------------------------------------------------
#define ASTR 72
#define A_QL (64*ASTR)
#define A_ST (2*A_QL)
#define A_MS (64*ASTR)
#define A_SS (4*A_MS)
#define ASMEM ((A_ST + 2*A_SS)*2)

__global__ void __launch_bounds__(128,2)
attn_mma(const __nv_bfloat16* __restrict__ Qh_, const __nv_bfloat16* __restrict__ Ql_,
         const __nv_bfloat16* __restrict__ Kh_, const __nv_bfloat16* __restrict__ Kl_,
         const __nv_bfloat16* __restrict__ Vh_, const __nv_bfloat16* __restrict__ Vl_,
         __nv_bfloat16* __restrict__ Ch, __nv_bfloat16* __restrict__ Cl){
    extern __shared__ __nv_bfloat16 sm[];
    const unsigned smb = (unsigned)__cvta_generic_to_shared(sm);
    const int tid = threadIdx.x, lane = tid&31, wid = tid>>5;
    const int qt = blockIdx.x, bh = blockIdx.y;
    const int b = bh>>5, h = bh&31, kvh = h>>2;
    const int qbase = b*2048 + qt*64;
    const int kbase0 = b*2048;
    const int kvcol = kvh*64;
    const __nv_bfloat16* kvsrc[4] = {Kh_, Kl_, Vh_, Vl_};

#pragma unroll
    for(int t=0;t<8;t++){
        int c = tid + t*128;
        int mat = c >> 9, idx = c & 511;
        int row = idx>>3, ch = idx&7;
        const __nv_bfloat16* src = (mat ? Ql_ : Qh_) + (size_t)(qbase+row)*2048 + h*64 + ch*8;
        unsigned dst = smb + (unsigned)((mat*A_QL + row*ASTR)*2 + ch*16);
        cpa16(dst, src);
    }
    cpcommit();

    auto load_kv = [&](int s, int kt){
#pragma unroll
        for(int t=0;t<16;t++){
            int c = tid + t*128;
            int mat = c>>9, idx = c&511;
            int row = idx>>3, ch = idx&7;
            const __nv_bfloat16* src = kvsrc[mat] + (size_t)(kbase0 + kt*64 + row)*512 + kvcol + ch*8;
            unsigned dst = smb + (unsigned)((A_ST + s*A_SS + mat*A_MS + row*ASTR)*2 + ch*16);
            cpa16(dst, src);
        }
        cpcommit();
    };
    load_kv(0, 0);
    load_kv(1, 1);

    asm volatile("cp.async.wait_group 2;":::"memory");
    __syncthreads();

    unsigned aqh[4][4], aql[4][4];
    const unsigned qro = (unsigned)(((wid*16 + (lane&15))*ASTR)*2 + (lane>>4)*16);
#pragma unroll
    for(int ks=0;ks<4;ks++){
        ldsm4(aqh[ks], smb + qro + ks*32);
        ldsm4(aql[ks], smb + (unsigned)(A_QL*2) + qro + ks*32);
    }

    float od[8][4];
#pragma unroll
    for(int nf=0;nf<8;nf++)
#pragma unroll
        for(int q=0;q<4;q++) od[nf][q]=0.f;
    float l0=0.f, l1=0.f;

    const unsigned bro_col = (unsigned)(((lane>>3)&1)*16);
    const unsigned bro_row = (unsigned)((lane&7) + (lane>>4)*8);
    const unsigned tro_row = (unsigned)((lane&7) + ((lane>>3)&1)*8);
    const unsigned tro_col = (unsigned)((lane>>4)*16);

    for(int kt=0;kt<32;kt++){
        asm volatile("cp.async.wait_group 1;":::"memory");
        __syncthreads();
        unsigned sb = smb + (unsigned)((A_ST + (kt&1)*A_SS)*2);

        float sc[8][4];
#pragma unroll
        for(int nf=0;nf<8;nf++)
#pragma unroll
            for(int q=0;q<4;q++) sc[nf][q]=0.f;

#pragma unroll
        for(int ks=0;ks<4;ks++){
#pragma unroll
            for(int ng=0;ng<4;ng++){
                unsigned kh4[4], kl4[4];
                unsigned ro = (unsigned)((ng*16 + bro_row)*ASTR*2) + bro_col + ks*32;
                ldsm4(kh4, sb + ro);
                ldsm4(kl4, sb + (unsigned)(A_MS*2) + ro);
                mma16816(sc[ng*2+0], aqh[ks], &kh4[0]);
                mma16816(sc[ng*2+1], aqh[ks], &kh4[2]);
                mma16816(sc[ng*2+0], aqh[ks], &kl4[0]);
                mma16816(sc[ng*2+1], aqh[ks], &kl4[2]);
                mma16816(sc[ng*2+0], aql[ks], &kh4[0]);
                mma16816(sc[ng*2+1], aql[ks], &kh4[2]);
            }
        }

#pragma unroll
        for(int ks=0;ks<4;ks++){
            unsigned aph[4], apl[4];
#pragma unroll
            for(int q=0;q<4;q++){
                int nf = ks*2 + (q>>1);
                float v0 = ex2f(sc[nf][(q&1)*2]);
                float v1 = ex2f(sc[nf][(q&1)*2+1]);
                if(q&1) l1 += v0 + v1; else l0 += v0 + v1;
                unsigned hh = packbf(v0, v1);
                float h0 = __uint_as_float(hh<<16);
                float h1 = __uint_as_float(hh & 0xffff0000u);
                aph[q] = hh;
                apl[q] = packbf(v0-h0, v1-h1);
            }
#pragma unroll
            for(int dg=0;dg<4;dg++){
                unsigned vh4[4], vl4[4];
                unsigned ro = (unsigned)((ks*16 + tro_row)*ASTR*2) + dg*32 + tro_col;
                ldsm4t(vh4, sb + (unsigned)(2*A_MS*2) + ro);
                ldsm4t(vl4, sb + (unsigned)(3*A_MS*2) + ro);
                mma16816(od[dg*2+0], aph, &vh4[0]);
                mma16816(od[dg*2+1], aph, &vh4[2]);
                mma16816(od[dg*2+0], aph, &vl4[0]);
                mma16816(od[dg*2+1], aph, &vl4[2]);
                mma16816(od[dg*2+0], apl, &vh4[0]);
                mma16816(od[dg*2+1], apl, &vh4[2]);
            }
        }

        __syncthreads();
        if(kt+2 < 32) load_kv(kt&1, kt+2); else cpcommit();
    }

    l0 += __shfl_xor_sync(0xffffffffu, l0, 1);
    l0 += __shfl_xor_sync(0xffffffffu, l0, 2);
    l1 += __shfl_xor_sync(0xffffffffu, l1, 1);
    l1 += __shfl_xor_sync(0xffffffffu, l1, 2);
    float inv0 = 1.f/l0, inv1 = 1.f/l1;
    const int r = lane>>2, cb = (lane&3)*2;
    size_t i0 = (size_t)(qbase + wid*16 + r)*2048 + h*64 + cb;
    size_t i1 = i0 + (size_t)8*2048;
#pragma unroll
    for(int nf=0;nf<8;nf++){
        float v0 = od[nf][0]*inv0, v1 = od[nf][1]*inv0;
        unsigned hh = packbf(v0, v1);
        float h0 = __uint_as_float(hh<<16), h1 = __uint_as_float(hh & 0xffff0000u);
        *(unsigned*)(Ch + i0 + nf*8) = hh;
        *(unsigned*)(Cl + i0 + nf*8) = packbf(v0-h0, v1-h1);
        float w0 = od[nf][2]*inv1, w1 = od[nf][3]*inv1;
        unsigned gg = packbf(w0, w1);
        float g0 = __uint_as_float(gg<<16), g1 = __uint_as_float(gg & 0xffff0000u);
        *(unsigned*)(Ch + i1 + nf*8) = gg;
        *(unsigned*)(Cl + i1 + nf*8) = packbf(w0-g0, w1-g1);
    }
}

// ---- host ----
typedef CUresult (*tmap_fn_t)(CUtensorMap*, CUtensorMapDataType, cuuint32_t, void*,
                              const cuuint64_t*, const cuuint64_t*, const cuuint32_t*, const cuuint32_t*,
                              CUtensorMapInterleave, CUtensorMapSwizzle, CUtensorMapL2promotion, CUtensorMapFloatOOBfill);

static void make2d(tmap_fn_t enc, CUtensorMap* m, void* ptr, cuuint64_t rows){
    cuuint64_t dims[2] = {2048ull, rows};
    cuuint64_t strd[1] = {4096ull};
    cuuint32_t box[2] = {64u, 128u};
    cuuint32_t es[2] = {1u, 1u};
    enc(m, CU_TENSOR_MAP_DATA_TYPE_BFLOAT16, 2, ptr, dims, strd, box, es,
        CU_TENSOR_MAP_INTERLEAVE_NONE, CU_TENSOR_MAP_SWIZZLE_128B,
        CU_TENSOR_MAP_L2_PROMOTION_L2_128B, CU_TENSOR_MAP_FLOAT_OOB_FILL_NONE);
}

extern "C" void kernel_launch(void* const* d_in, const int* in_sizes, int n_in,
                              void* d_out, int out_size){
    const float* x  = (const float*)d_in[0];
    const float* Wq = (const float*)d_in[1];
    const float* Wk = (const float*)d_in[2];
    const float* Wv = (const float*)d_in[3];
    const float* Wo = (const float*)d_in[4];
    float* out = (float*)d_out;

    void *xh,*xl,*wh,*wl,*woh,*wol,*qh,*ql,*kh,*kl,*vh,*vl;
    cudaGetSymbolAddress(&xh,g_xh);  cudaGetSymbolAddress(&xl,g_xl);
    cudaGetSymbolAddress(&wh,g_wqkvh); cudaGetSymbolAddress(&wl,g_wqkvl);
    cudaGetSymbolAddress(&woh,g_woh);cudaGetSymbolAddress(&wol,g_wol);
    cudaGetSymbolAddress(&qh,g_qh);  cudaGetSymbolAddress(&ql,g_ql);
    cudaGetSymbolAddress(&kh,g_kh);  cudaGetSymbolAddress(&kl,g_kl);
    cudaGetSymbolAddress(&vh,g_vh);  cudaGetSymbolAddress(&vl,g_vl);

    tmap_fn_t enc = 0;
    cudaDriverEntryPointQueryResult qr;
    cudaGetDriverEntryPointByVersion("cuTensorMapEncodeTiled", (void**)&enc, 12000,
                                     cudaEnableDefault, &qr);

    static CUtensorMap tXh,tXl,tWh,tWl,tOh,tOl;
    make2d(enc,&tXh,xh,4096);  make2d(enc,&tXl,xl,4096);
    make2d(enc,&tWh,wh,3072);  make2d(enc,&tWl,wl,3072);
    make2d(enc,&tOh,woh,2048); make2d(enc,&tOl,wol,2048);

    cudaFuncSetAttribute(gemm_tma, cudaFuncAttributeMaxDynamicSharedMemorySize, GSMEM);
    cudaFuncSetAttribute(attn_mma, cudaFuncAttributeMaxDynamicSharedMemorySize, ASMEM);

    wsplitAll<<<dim3(160,64),dim3(32,8)>>>(Wq, Wk, Wv, Wo,
        (__nv_bfloat16*)wh, (__nv_bfloat16*)wl, (__nv_bfloat16*)woh, (__nv_bfloat16*)wol);
    fsplit<<<512,256>>>((const float4*)x, (ull*)xh, (ull*)xl, 4096*2048/4, 1.0f);

    gemm_tma<<<dim3(24,32),256,GSMEM>>>(tXh,tXl,tWh,tWl, nullptr,
        (__nv_bfloat16*)qh,(__nv_bfloat16*)ql,
        (__nv_bfloat16*)kh,(__nv_bfloat16*)kl,
        (__nv_bfloat16*)vh,(__nv_bfloat16*)vl);

    attn_mma<<<dim3(32,64),128,ASMEM>>>((__nv_bfloat16*)qh,(__nv_bfloat16*)ql,
        (__nv_bfloat16*)kh,(__nv_bfloat16*)kl,
        (__nv_bfloat16*)vh,(__nv_bfloat16*)vl,
        (__nv_bfloat16*)xh,(__nv_bfloat16*)xl);

    gemm_tma<<<dim3(16,32),256,GSMEM>>>(tXh,tXl,tOh,tOl, out,
        nullptr,nullptr,nullptr,nullptr,nullptr,nullptr);
}

// round 14
// speedup vs baseline: 1.7303x; 1.3495x over previous
#include <cuda_runtime.h>
#include <cuda.h>
#include <cuda_fp16.h>
#include <math.h>

// ---- scratch (fp16) ----
__device__ __half g_x[4096*2048];                 // x trunc; reused for ctx
__device__ __half g_wqkvh[3072*2048], g_wqkvl[3072*2048];
__device__ __half g_woh[2048*2048],   g_wol[2048*2048];
__device__ __half g_q[4096*2048];
__device__ __half g_kh[4096*512],  g_kl[4096*512];
__device__ __half g_vh[4096*512],  g_vl[4096*512];

#define QSCALE (0.125f * 1.4426950408889634f)   // 1/sqrt(64) * log2(e)

__device__ __forceinline__ unsigned packhf(float lo, float hi){
    unsigned r; asm("cvt.rn.f16x2.f32 %0, %1, %2;":"=r"(r):"f"(hi),"f"(lo)); return r;
}
__device__ __forceinline__ void splithf(float v0, float v1, unsigned &hh, unsigned &ll){
    __half2 h = __float22half2_rn(make_float2(v0,v1));
    float2 b = __half22float2(h);
    hh = *(unsigned*)&h;
    __half2 l = __float22half2_rn(make_float2(v0-b.x, v1-b.y));
    ll = *(unsigned*)&l;
}

// fp32 -> fp16 truncate (x)
__global__ void __launch_bounds__(256) ftrunc(const float4* __restrict__ in,
                                              uint2* __restrict__ out, int n4){
    int i = blockIdx.x*blockDim.x + threadIdx.x, st = gridDim.x*blockDim.x;
    for(; i < n4; i += st){
        float4 v = in[i];
        uint2 o;
        o.x = packhf(v.x, v.y);
        o.y = packhf(v.z, v.w);
        out[i] = o;
    }
}

// all 4 weight transposed fp16 hi/lo splits in one launch
__global__ void wsplitAll(const float* __restrict__ Wq, const float* __restrict__ Wk,
                          const float* __restrict__ Wv, const float* __restrict__ Wo,
                          __half* __restrict__ qkvh, __half* __restrict__ qkvl,
                          __half* __restrict__ woh, __half* __restrict__ wol){
    __shared__ float t[32][33];
    int bx = blockIdx.x;
    const float* W; __half *Th, *Tl; int N, n0;
    if(bx < 64){ W=Wq; Th=qkvh; Tl=qkvl; N=2048; n0=bx*32; }
    else if(bx < 80){ W=Wk; Th=qkvh+(size_t)2048*2048; Tl=qkvl+(size_t)2048*2048; N=512; n0=(bx-64)*32; }
    else if(bx < 96){ W=Wv; Th=qkvh+(size_t)2560*2048; Tl=qkvl+(size_t)2560*2048; N=512; n0=(bx-80)*32; }
    else { W=Wo; Th=woh; Tl=wol; N=2048; n0=(bx-96)*32; }
    int k0 = blockIdx.y*32;
    int tx = threadIdx.x, ty = threadIdx.y;
#pragma unroll
    for(int p=0;p<32;p+=8) t[ty+p][tx] = W[(size_t)(k0+ty+p)*N + n0+tx];
    __syncthreads();
#pragma unroll
    for(int p=0;p<32;p+=8){
        float v = t[tx][ty+p];
        __half h = __float2half_rn(v);
        __half l = __float2half_rn(v - __half2float(h));
        Th[(size_t)(n0+ty+p)*2048 + k0+tx] = h;
        Tl[(size_t)(n0+ty+p)*2048 + k0+tx] = l;
    }
}

// ---- helpers ----
__device__ __forceinline__ void ldsm4(unsigned* r, unsigned a){
    asm volatile("ldmatrix.sync.aligned.m8n8.x4.shared.b16 {%0,%1,%2,%3},[%4];"
                 :"=r"(r[0]),"=r"(r[1]),"=r"(r[2]),"=r"(r[3]):"r"(a));
}
__device__ __forceinline__ void ldsm4t(unsigned* r, unsigned a){
    asm volatile("ldmatrix.sync.aligned.m8n8.x4.trans.shared.b16 {%0,%1,%2,%3},[%4];"
                 :"=r"(r[0]),"=r"(r[1]),"=r"(r[2]),"=r"(r[3]):"r"(a));
}
__device__ __forceinline__ void mmaf16(float* c, const unsigned* a, const unsigned* b){
    asm volatile("mma.sync.aligned.m16n8k16.row.col.f32.f16.f16.f32 "
                 "{%0,%1,%2,%3},{%4,%5,%6,%7},{%8,%9},{%0,%1,%2,%3};"
                 :"+f"(c[0]),"+f"(c[1]),"+f"(c[2]),"+f"(c[3])
                 :"r"(a[0]),"r"(a[1]),"r"(a[2]),"r"(a[3]),"r"(b[0]),"r"(b[1]));
}
__device__ __forceinline__ void cpa16(unsigned d, const void* s){
    asm volatile("cp.async.cg.shared.global [%0],[%1],16;"::"r"(d),"l"(s):"memory");
}
__device__ __forceinline__ void cpcommit(){ asm volatile("cp.async.commit_group;":::"memory"); }
__device__ __forceinline__ float ex2f(float x){
    float r; asm("ex2.approx.ftz.f32 %0,%1;":"=f"(r):"f"(x)); return r;
}
__device__ __forceinline__ void mbar_init(unsigned a,unsigned c){
    asm volatile("mbarrier.init.shared.b64 [%0],%1;"::"r"(a),"r"(c):"memory");
}
__device__ __forceinline__ void mbar_expect(unsigned a,unsigned b){
    asm volatile("mbarrier.arrive.expect_tx.shared.b64 _,[%0],%1;"::"r"(a),"r"(b):"memory");
}
__device__ __forceinline__ void mbar_wait(unsigned a,unsigned p){
    asm volatile("{\n\t.reg .pred P;\nW_%=:\n\t"
                 "mbarrier.try_wait.parity.acquire.cta.shared::cta.b64 P,[%0],%1;\n\t"
                 "@!P bra W_%=;\n\t}"::"r"(a),"r"(p):"memory");
}
__device__ __forceinline__ void tma2(unsigned s,const CUtensorMap* m,int cx,int cy,unsigned mb){
    asm volatile("cp.async.bulk.tensor.2d.shared::cta.global.tile.mbarrier::complete_tx::bytes "
                 "[%0],[%1,{%2,%3}],[%4];"
                 ::"r"(s),"l"(m),"r"(cx),"r"(cy),"r"(mb):"memory");
}

// ---------------------------------------------------------------------------
// TMA-fed fp16x2 GEMM: C = A[M][2048] @ B[N][2048]^T,
// A truncated fp16 (1 tensor), B split hi/lo (2 tensors). 2 MMAs per k16.
// CTA 128x128, K-chunk 64, 2 stages x 48KB, SW128.
// ---------------------------------------------------------------------------
#define GSMEM (1024 + 2*49152)

__global__ void __launch_bounds__(256,1)
gemm_tma(const __grid_constant__ CUtensorMap tA,
         const __grid_constant__ CUtensorMap tBh, const __grid_constant__ CUtensorMap tBl,
         float* __restrict__ Cf,
         __half* __restrict__ q1,
         __half* __restrict__ kh, __half* __restrict__ kl,
         __half* __restrict__ vh, __half* __restrict__ vl){
    extern __shared__ char smraw[];
    unsigned smu; asm("{ .reg .u64 t; cvta.to.shared.u64 t,%1; cvt.u32.u64 %0,t; }":"=r"(smu):"l"(smraw));
    const unsigned base = (smu + 1023u) & ~1023u;
    const unsigned mb0 = base, mb1 = base + 8;
    const unsigned tiles = base + 1024;
    const int tid = threadIdx.x, lane = tid & 31, wid = tid >> 5;
    const int wm = wid >> 1, wn = wid & 1;
    const int bm = blockIdx.y * 128, bn = blockIdx.x * 128;

    if(tid==0){ mbar_init(mb0,1); mbar_init(mb1,1); }
    __syncthreads();

    auto issue = [&](int s, int k0){
        unsigned mb = s ? mb1 : mb0;
        mbar_expect(mb, 49152u);
        unsigned dst = tiles + (unsigned)s*49152u;
        tma2(dst,          &tA,  k0, bm, mb);
        tma2(dst + 16384u, &tBh, k0, bn, mb);
        tma2(dst + 32768u, &tBl, k0, bn, mb);
    };
    if(tid==0){ issue(0, 0); issue(1, 64); }

    float acc[2][8][4];
#pragma unroll
    for(int i=0;i<2;i++)
#pragma unroll
        for(int j=0;j<8;j++)
#pragma unroll
            for(int q=0;q<4;q++) acc[i][j][q]=0.f;

    unsigned arow[2], axor[2], brow[4], bxor[4];
#pragma unroll
    for(int mf=0;mf<2;mf++){
        int r = wm*32 + mf*16 + (lane&7) + ((lane>>3)&1)*8;
        arow[mf] = (unsigned)(r*128); axor[mf] = (unsigned)((r&7)<<4);
    }
#pragma unroll
    for(int jj=0;jj<4;jj++){
        int r = wn*64 + jj*16 + (lane&7) + (lane>>4)*8;
        brow[jj] = (unsigned)(r*128); bxor[jj] = (unsigned)((r&7)<<4);
    }
    const unsigned acol = (unsigned)((lane>>4)*16);
    const unsigned bcol = (unsigned)(((lane>>3)&1)*16);

    int ph[2] = {0,0};
    for(int it=0; it<32; ++it){
        int s = it & 1;
        mbar_wait(s?mb1:mb0, ph[s]); ph[s] ^= 1;
        unsigned sb = tiles + (unsigned)s*49152u;
#pragma unroll
        for(int ks=0;ks<4;ks++){
            unsigned ah[2][4], bh[4][4], bl[4][4];
#pragma unroll
            for(int mf=0;mf<2;mf++){
                unsigned c = (acol + ks*32);
                ldsm4(ah[mf], sb + arow[mf] + (c ^ axor[mf]));
            }
#pragma unroll
            for(int jj=0;jj<4;jj++){
                unsigned c = (bcol + ks*32);
                ldsm4(bh[jj], sb + 16384u + brow[jj] + (c ^ bxor[jj]));
                ldsm4(bl[jj], sb + 32768u + brow[jj] + (c ^ bxor[jj]));
            }
#pragma unroll
            for(int mf=0;mf<2;mf++)
#pragma unroll
                for(int nf=0;nf<8;nf++){
                    const unsigned* bhf = &bh[nf>>1][(nf&1)*2];
                    const unsigned* blf = &bl[nf>>1][(nf&1)*2];
                    mmaf16(acc[mf][nf], ah[mf], bhf);
                    mmaf16(acc[mf][nf], ah[mf], blf);
                }
        }
        __syncthreads();
        if(it+2 < 32 && tid==0) issue(s, (it+2)*64);
    }

    const int r0 = bm + wm*32 + (lane>>2);
    if(Cf){
        const int c0 = bn + wn*64 + (lane&3)*2;
#pragma unroll
        for(int mf=0;mf<2;mf++)
#pragma unroll
            for(int nf=0;nf<8;nf++){
                float* p0 = Cf + (size_t)(r0 + mf*16)*2048 + c0 + nf*8;
                float* p1 = Cf + (size_t)(r0 + mf*16 + 8)*2048 + c0 + nf*8;
                *(float2*)p0 = make_float2(acc[mf][nf][0], acc[mf][nf][1]);
                *(float2*)p1 = make_float2(acc[mf][nf][2], acc[mf][nf][3]);
            }
    } else if(bn < 2048){
        // Q: truncated fp16 with QSCALE
        const int c0 = bn + wn*64 + (lane&3)*2;
#pragma unroll
        for(int mf=0;mf<2;mf++)
#pragma unroll
            for(int nf=0;nf<8;nf++)
#pragma unroll
                for(int hl=0;hl<2;hl++){
                    float v0 = acc[mf][nf][hl*2]*QSCALE, v1 = acc[mf][nf][hl*2+1]*QSCALE;
                    size_t idx = (size_t)(r0 + mf*16 + hl*8)*2048 + c0 + nf*8;
                    *(unsigned*)(q1 + idx) = packhf(v0, v1);
                }
    } else {
        __half *Oh, *Ol; int cbase;
        if(bn < 2560){ Oh=kh; Ol=kl; cbase=bn-2048; }
        else { Oh=vh; Ol=vl; cbase=bn-2560; }
        const int c0 = cbase + wn*64 + (lane&3)*2;
#pragma unroll
        for(int mf=0;mf<2;mf++)
#pragma unroll
            for(int nf=0;nf<8;nf++)
#pragma unroll
                for(int hl=0;hl<2;hl++){
                    unsigned hh, ll;
                    splithf(acc[mf][nf][hl*2], acc[mf][nf][hl*2+1], hh, ll);
                    size_t idx = (size_t)(r0 + mf*16 + hl*8)*512 + c0 + nf*8;
                    *(unsigned*)(Oh + idx) = hh;
                    *(unsigned*)(Ol + idx) = ll;
                }
    }
}

// ---------------------------------------------------------------------------
// fp16x2 flash attention: q-tile 64, kv-tile 64, 2-stage, 2 CTAs/SM.
// QK: q(trunc)·(kh+kl) = 4 MMAs/ng ; PV: p(trunc)·(vh+vl) = 4 MMAs/dg.
// ---------------------------------------------------------------------------
#define ASTR 72
#define A_Q  (64*ASTR)
#define A_MS (64*ASTR)
#define A_SS (4*A_MS)
#define ASMEM ((A_Q + 2*A_SS)*2)   // 82944 B -> 2 CTAs/SM

__global__ void __launch_bounds__(128,2)
attn_mma(const __half* __restrict__ Q1, const __half* __restrict__ Kh_,
         const __half* __restrict__ Kl_, const __half* __restrict__ Vh_,
         const __half* __restrict__ Vl_, __half* __restrict__ C1){
    extern __shared__ __half sm[];
    const unsigned smb = (unsigned)__cvta_generic_to_shared(sm);
    const int tid = threadIdx.x, lane = tid&31, wid = tid>>5;
    const int qt = blockIdx.x, bh = blockIdx.y;
    const int b = bh>>5, h = bh&31, kvh = h>>2;
    const int qbase = b*2048 + qt*64;
    const int kbase0 = b*2048;
    const int kvcol = kvh*64;
    const __half* kvsrc[4] = {Kh_, Kl_, Vh_, Vl_};

    // Q tile: 64 rows x 64 cols = 512 chunks / 128 thr = 4 iters
#pragma unroll
    for(int t=0;t<4;t++){
        int c = tid + t*128;
        int row = c>>3, ch = c&7;
        const __half* src = Q1 + (size_t)(qbase+row)*2048 + h*64 + ch*8;
        unsigned dst = smb + (unsigned)((row*ASTR)*2 + ch*16);
        cpa16(dst, src);
    }
    cpcommit();

    auto load_kv = [&](int s, int kt){
#pragma unroll
        for(int t=0;t<16;t++){
            int c = tid + t*128;
            int mat = c>>9, idx = c&511;
            int row = idx>>3, ch = idx&7;
            const __half* src = kvsrc[mat] + (size_t)(kbase0 + kt*64 + row)*512 + kvcol + ch*8;
            unsigned dst = smb + (unsigned)((A_Q + s*A_SS + mat*A_MS + row*ASTR)*2 + ch*16);
            cpa16(dst, src);
        }
        cpcommit();
    };
    load_kv(0, 0);
    load_kv(1, 1);

    asm volatile("cp.async.wait_group 2;":::"memory");
    __syncthreads();

    unsigned aq[4][4];
    const unsigned qro = (unsigned)(((wid*16 + (lane&15))*ASTR)*2 + (lane>>4)*16);
#pragma unroll
    for(int ks=0;ks<4;ks++) ldsm4(aq[ks], smb + qro + ks*32);

    float od[8][4];
#pragma unroll
    for(int nf=0;nf<8;nf++)
#pragma unroll
        for(int q=0;q<4;q++) od[nf][q]=0.f;
    float l0=0.f, l1=0.f;

    const unsigned bro_col = (unsigned)(((lane>>3)&1)*16);
    const unsigned bro_row = (unsigned)((lane&7) + (lane>>4)*8);
    const unsigned tro_row = (unsigned)((lane&7) + ((lane>>3)&1)*8);
    const unsigned tro_col = (unsigned)((lane>>4)*16);

    for(int kt=0;kt<32;kt++){
        asm volatile("cp.async.wait_group 1;":::"memory");
        __syncthreads();
        unsigned sb = smb + (unsigned)((A_Q + (kt&1)*A_SS)*2);

        float sc[8][4];
#pragma unroll
        for(int nf=0;nf<8;nf++)
#pragma unroll
            for(int q=0;q<4;q++) sc[nf][q]=0.f;

#pragma unroll
        for(int ks=0;ks<4;ks++){
#pragma unroll
            for(int ng=0;ng<4;ng++){
                unsigned kh4[4], kl4[4];
                unsigned ro = (unsigned)((ng*16 + bro_row)*ASTR*2) + bro_col + ks*32;
                ldsm4(kh4, sb + ro);
                ldsm4(kl4, sb + (unsigned)(A_MS*2) + ro);
                mmaf16(sc[ng*2+0], aq[ks], &kh4[0]);
                mmaf16(sc[ng*2+1], aq[ks], &kh4[2]);
                mmaf16(sc[ng*2+0], aq[ks], &kl4[0]);
                mmaf16(sc[ng*2+1], aq[ks], &kl4[2]);
            }
        }

#pragma unroll
        for(int ks=0;ks<4;ks++){
            unsigned aph[4];
#pragma unroll
            for(int q=0;q<4;q++){
                int nf = ks*2 + (q>>1);
                float v0 = ex2f(sc[nf][(q&1)*2]);
                float v1 = ex2f(sc[nf][(q&1)*2+1]);
                if(q&1) l1 += v0 + v1; else l0 += v0 + v1;
                aph[q] = packhf(v0, v1);
            }
#pragma unroll
            for(int dg=0;dg<4;dg++){
                unsigned vh4[4], vl4[4];
                unsigned ro = (unsigned)((ks*16 + tro_row)*ASTR*2) + dg*32 + tro_col;
                ldsm4t(vh4, sb + (unsigned)(2*A_MS*2) + ro);
                ldsm4t(vl4, sb + (unsigned)(3*A_MS*2) + ro);
                mmaf16(od[dg*2+0], aph, &vh4[0]);
                mmaf16(od[dg*2+1], aph, &vh4[2]);
                mmaf16(od[dg*2+0], aph, &vl4[0]);
                mmaf16(od[dg*2+1], aph, &vl4[2]);
            }
        }

        __syncthreads();
        if(kt+2 < 32) load_kv(kt&1, kt+2); else cpcommit();
    }

    l0 += __shfl_xor_sync(0xffffffffu, l0, 1);
    l0 += __shfl_xor_sync(0xffffffffu, l0, 2);
    l1 += __shfl_xor_sync(0xffffffffu, l1, 1);
    l1 += __shfl_xor_sync(0xffffffffu, l1, 2);
    float inv0 = 1.f/l0, inv1 = 1.f/l1;
    const int r = lane>>2, cb = (lane&3)*2;
    size_t i0 = (size_t)(qbase + wid*16 + r)*2048 + h*64 + cb;
    size_t i1 = i0 + (size_t)8*2048;
#pragma unroll
    for(int nf=0;nf<8;nf++){
        *(unsigned*)(C1 + i0 + nf*8) = packhf(od[nf][0]*inv0, od[nf][1]*inv0);
        *(unsigned*)(C1 + i1 + nf*8) = packhf(od[nf][2]*inv1, od[nf][3]*inv1);
    }
}

// ---- host ----
typedef CUresult (*tmap_fn_t)(CUtensorMap*, CUtensorMapDataType, cuuint32_t, void*,
                              const cuuint64_t*, const cuuint64_t*, const cuuint32_t*, const cuuint32_t*,
                              CUtensorMapInterleave, CUtensorMapSwizzle, CUtensorMapL2promotion, CUtensorMapFloatOOBfill);

static void make2d(tmap_fn_t enc, CUtensorMap* m, void* ptr, cuuint64_t rows){
    cuuint64_t dims[2] = {2048ull, rows};
    cuuint64_t strd[1] = {4096ull};
    cuuint32_t box[2] = {64u, 128u};
    cuuint32_t es[2] = {1u, 1u};
    enc(m, CU_TENSOR_MAP_DATA_TYPE_FLOAT16, 2, ptr, dims, strd, box, es,
        CU_TENSOR_MAP_INTERLEAVE_NONE, CU_TENSOR_MAP_SWIZZLE_128B,
        CU_TENSOR_MAP_L2_PROMOTION_L2_128B, CU_TENSOR_MAP_FLOAT_OOB_FILL_NONE);
}

extern "C" void kernel_launch(void* const* d_in, const int* in_sizes, int n_in,
                              void* d_out, int out_size){
    const float* x  = (const float*)d_in[0];
    const float* Wq = (const float*)d_in[1];
    const float* Wk = (const float*)d_in[2];
    const float* Wv = (const float*)d_in[3];
    const float* Wo = (const float*)d_in[4];
    float* out = (float*)d_out;

    void *xb,*wh,*wl,*woh,*wol,*q1,*kh,*kl,*vh,*vl;
    cudaGetSymbolAddress(&xb,g_x);
    cudaGetSymbolAddress(&wh,g_wqkvh); cudaGetSymbolAddress(&wl,g_wqkvl);
    cudaGetSymbolAddress(&woh,g_woh);  cudaGetSymbolAddress(&wol,g_wol);
    cudaGetSymbolAddress(&q1,g_q);
    cudaGetSymbolAddress(&kh,g_kh);  cudaGetSymbolAddress(&kl,g_kl);
    cudaGetSymbolAddress(&vh,g_vh);  cudaGetSymbolAddress(&vl,g_vl);

    tmap_fn_t enc = 0;
    cudaDriverEntryPointQueryResult qr;
    cudaGetDriverEntryPointByVersion("cuTensorMapEncodeTiled", (void**)&enc, 12000,
                                     cudaEnableDefault, &qr);

    static CUtensorMap tX,tWh,tWl,tOh,tOl;
    make2d(enc,&tX,xb,4096);
    make2d(enc,&tWh,wh,3072);  make2d(enc,&tWl,wl,3072);
    make2d(enc,&tOh,woh,2048); make2d(enc,&tOl,wol,2048);

    cudaFuncSetAttribute(gemm_tma, cudaFuncAttributeMaxDynamicSharedMemorySize, GSMEM);
    cudaFuncSetAttribute(attn_mma, cudaFuncAttributeMaxDynamicSharedMemorySize, ASMEM);

    wsplitAll<<<dim3(160,64),dim3(32,8)>>>(Wq, Wk, Wv, Wo,
        (__half*)wh, (__half*)wl, (__half*)woh, (__half*)wol);
    ftrunc<<<512,256>>>((const float4*)x, (uint2*)xb, 4096*2048/4);

    // fused QKV projection
    gemm_tma<<<dim3(24,32),256,GSMEM>>>(tX,tWh,tWl, nullptr,
        (__half*)q1, (__half*)kh,(__half*)kl, (__half*)vh,(__half*)vl);

    // attention -> ctx (reuse g_x)
    attn_mma<<<dim3(32,64),128,ASMEM>>>((__half*)q1,
        (__half*)kh,(__half*)kl, (__half*)vh,(__half*)vl, (__half*)xb);

    // O projection -> fp32 out
    gemm_tma<<<dim3(16,32),256,GSMEM>>>(tX,tOh,tOl, out,
        nullptr,nullptr,nullptr,nullptr,nullptr);
}

// round 15
// speedup vs baseline: 3.0785x; 1.7792x over previous
#include <cuda_runtime.h>
#include <cuda.h>
#include <cuda_fp16.h>
#include <math.h>

// ---- scratch (fp16) ----
__device__ __half g_x[4096*2048];                 // x trunc; reused for ctx
__device__ __half g_w[3072*2048];                 // concat WqT|WkT|WvT trunc
__device__ __half g_wo[2048*2048];
__device__ __half g_q[4096*2048];
__device__ __half g_k[4096*512];
__device__ __half g_v[4096*512];

#define QSCALE (0.125f * 1.4426950408889634f)   // 1/sqrt(64) * log2(e)

__device__ __forceinline__ unsigned packhf(float lo, float hi){
    unsigned r; asm("cvt.rn.f16x2.f32 %0, %1, %2;":"=r"(r):"f"(hi),"f"(lo)); return r;
}

// fp32 -> fp16 truncate
__global__ void __launch_bounds__(256) ftrunc(const float4* __restrict__ in,
                                              uint2* __restrict__ out, int n4){
    int i = blockIdx.x*blockDim.x + threadIdx.x, st = gridDim.x*blockDim.x;
    for(; i < n4; i += st){
        float4 v = in[i];
        uint2 o;
        o.x = packhf(v.x, v.y);
        o.y = packhf(v.z, v.w);
        out[i] = o;
    }
}

// all 4 weights: transpose + fp16 truncate, one launch
__global__ void wtruncAll(const float* __restrict__ Wq, const float* __restrict__ Wk,
                          const float* __restrict__ Wv, const float* __restrict__ Wo,
                          __half* __restrict__ qkv, __half* __restrict__ wo){
    __shared__ float t[32][33];
    int bx = blockIdx.x;
    const float* W; __half *T; int N, n0;
    if(bx < 64){ W=Wq; T=qkv; N=2048; n0=bx*32; }
    else if(bx < 80){ W=Wk; T=qkv+(size_t)2048*2048; N=512; n0=(bx-64)*32; }
    else if(bx < 96){ W=Wv; T=qkv+(size_t)2560*2048; N=512; n0=(bx-80)*32; }
    else { W=Wo; T=wo; N=2048; n0=(bx-96)*32; }
    int k0 = blockIdx.y*32;
    int tx = threadIdx.x, ty = threadIdx.y;
#pragma unroll
    for(int p=0;p<32;p+=8) t[ty+p][tx] = W[(size_t)(k0+ty+p)*N + n0+tx];
    __syncthreads();
#pragma unroll
    for(int p=0;p<32;p+=8)
        T[(size_t)(n0+ty+p)*2048 + k0+tx] = __float2half_rn(t[tx][ty+p]);
}

// ---- helpers ----
__device__ __forceinline__ void ldsm4(unsigned* r, unsigned a){
    asm volatile("ldmatrix.sync.aligned.m8n8.x4.shared.b16 {%0,%1,%2,%3},[%4];"
                 :"=r"(r[0]),"=r"(r[1]),"=r"(r[2]),"=r"(r[3]):"r"(a));
}
__device__ __forceinline__ void ldsm4t(unsigned* r, unsigned a){
    asm volatile("ldmatrix.sync.aligned.m8n8.x4.trans.shared.b16 {%0,%1,%2,%3},[%4];"
                 :"=r"(r[0]),"=r"(r[1]),"=r"(r[2]),"=r"(r[3]):"r"(a));
}
__device__ __forceinline__ void mmaf16(float* c, const unsigned* a, const unsigned* b){
    asm volatile("mma.sync.aligned.m16n8k16.row.col.f32.f16.f16.f32 "
                 "{%0,%1,%2,%3},{%4,%5,%6,%7},{%8,%9},{%0,%1,%2,%3};"
                 :"+f"(c[0]),"+f"(c[1]),"+f"(c[2]),"+f"(c[3])
                 :"r"(a[0]),"r"(a[1]),"r"(a[2]),"r"(a[3]),"r"(b[0]),"r"(b[1]));
}
__device__ __forceinline__ void cpa16(unsigned d, const void* s){
    asm volatile("cp.async.cg.shared.global [%0],[%1],16;"::"r"(d),"l"(s):"memory");
}
__device__ __forceinline__ void cpcommit(){ asm volatile("cp.async.commit_group;":::"memory"); }
__device__ __forceinline__ float ex2f(float x){
    float r; asm("ex2.approx.ftz.f32 %0,%1;":"=f"(r):"f"(x)); return r;
}
__device__ __forceinline__ void mbar_init(unsigned a,unsigned c){
    asm volatile("mbarrier.init.shared.b64 [%0],%1;"::"r"(a),"r"(c):"memory");
}
__device__ __forceinline__ void mbar_expect(unsigned a,unsigned b){
    asm volatile("mbarrier.arrive.expect_tx.shared.b64 _,[%0],%1;"::"r"(a),"r"(b):"memory");
}
__device__ __forceinline__ void mbar_wait(unsigned a,unsigned p){
    asm volatile("{\n\t.reg .pred P;\nW_%=:\n\t"
                 "mbarrier.try_wait.parity.acquire.cta.shared::cta.b64 P,[%0],%1;\n\t"
                 "@!P bra W_%=;\n\t}"::"r"(a),"r"(p):"memory");
}
__device__ __forceinline__ void tma2(unsigned s,const CUtensorMap* m,int cx,int cy,unsigned mb){
    asm volatile("cp.async.bulk.tensor.2d.shared::cta.global.tile.mbarrier::complete_tx::bytes "
                 "[%0],[%1,{%2,%3}],[%4];"
                 ::"r"(s),"l"(m),"r"(cx),"r"(cy),"r"(mb):"memory");
}

// ---------------------------------------------------------------------------
// TMA-fed fp16 GEMM: C = A[M][2048] @ B[N][2048]^T, 1 MMA per k16.
// CTA 128x128, K-chunk 64, 2 stages x 32KB, SW128.
// ---------------------------------------------------------------------------
#define GSMEM (1024 + 2*32768)

__global__ void __launch_bounds__(256,1)
gemm_tma(const __grid_constant__ CUtensorMap tA,
         const __grid_constant__ CUtensorMap tB,
         float* __restrict__ Cf,
         __half* __restrict__ q1, __half* __restrict__ k1, __half* __restrict__ v1){
    extern __shared__ char smraw[];
    unsigned smu; asm("{ .reg .u64 t; cvta.to.shared.u64 t,%1; cvt.u32.u64 %0,t; }":"=r"(smu):"l"(smraw));
    const unsigned base = (smu + 1023u) & ~1023u;
    const unsigned mb0 = base, mb1 = base + 8;
    const unsigned tiles = base + 1024;
    const int tid = threadIdx.x, lane = tid & 31, wid = tid >> 5;
    const int wm = wid >> 1, wn = wid & 1;
    const int bm = blockIdx.y * 128, bn = blockIdx.x * 128;

    if(tid==0){ mbar_init(mb0,1); mbar_init(mb1,1); }
    __syncthreads();

    auto issue = [&](int s, int k0){
        unsigned mb = s ? mb1 : mb0;
        mbar_expect(mb, 32768u);
        unsigned dst = tiles + (unsigned)s*32768u;
        tma2(dst,          &tA, k0, bm, mb);
        tma2(dst + 16384u, &tB, k0, bn, mb);
    };
    if(tid==0){ issue(0, 0); issue(1, 64); }

    float acc[2][8][4];
#pragma unroll
    for(int i=0;i<2;i++)
#pragma unroll
        for(int j=0;j<8;j++)
#pragma unroll
            for(int q=0;q<4;q++) acc[i][j][q]=0.f;

    unsigned arow[2], axor[2], brow[4], bxor[4];
#pragma unroll
    for(int mf=0;mf<2;mf++){
        int r = wm*32 + mf*16 + (lane&7) + ((lane>>3)&1)*8;
        arow[mf] = (unsigned)(r*128); axor[mf] = (unsigned)((r&7)<<4);
    }
#pragma unroll
    for(int jj=0;jj<4;jj++){
        int r = wn*64 + jj*16 + (lane&7) + (lane>>4)*8;
        brow[jj] = (unsigned)(r*128); bxor[jj] = (unsigned)((r&7)<<4);
    }
    const unsigned acol = (unsigned)((lane>>4)*16);
    const unsigned bcol = (unsigned)(((lane>>3)&1)*16);

    int ph[2] = {0,0};
    for(int it=0; it<32; ++it){
        int s = it & 1;
        mbar_wait(s?mb1:mb0, ph[s]); ph[s] ^= 1;
        unsigned sb = tiles + (unsigned)s*32768u;
#pragma unroll
        for(int ks=0;ks<4;ks++){
            unsigned ah[2][4], bh[4][4];
#pragma unroll
            for(int mf=0;mf<2;mf++){
                unsigned c = (acol + ks*32);
                ldsm4(ah[mf], sb + arow[mf] + (c ^ axor[mf]));
            }
#pragma unroll
            for(int jj=0;jj<4;jj++){
                unsigned c = (bcol + ks*32);
                ldsm4(bh[jj], sb + 16384u + brow[jj] + (c ^ bxor[jj]));
            }
#pragma unroll
            for(int mf=0;mf<2;mf++)
#pragma unroll
                for(int nf=0;nf<8;nf++)
                    mmaf16(acc[mf][nf], ah[mf], &bh[nf>>1][(nf&1)*2]);
        }
        __syncthreads();
        if(it+2 < 32 && tid==0) issue(s, (it+2)*64);
    }

    const int r0 = bm + wm*32 + (lane>>2);
    if(Cf){
        const int c0 = bn + wn*64 + (lane&3)*2;
#pragma unroll
        for(int mf=0;mf<2;mf++)
#pragma unroll
            for(int nf=0;nf<8;nf++){
                float* p0 = Cf + (size_t)(r0 + mf*16)*2048 + c0 + nf*8;
                float* p1 = Cf + (size_t)(r0 + mf*16 + 8)*2048 + c0 + nf*8;
                *(float2*)p0 = make_float2(acc[mf][nf][0], acc[mf][nf][1]);
                *(float2*)p1 = make_float2(acc[mf][nf][2], acc[mf][nf][3]);
            }
    } else {
        __half* O; int No, cbase; float scl;
        if(bn < 2048){ O=q1; No=2048; scl=QSCALE; cbase=bn; }
        else if(bn < 2560){ O=k1; No=512; scl=1.f; cbase=bn-2048; }
        else { O=v1; No=512; scl=1.f; cbase=bn-2560; }
        const int c0 = cbase + wn*64 + (lane&3)*2;
#pragma unroll
        for(int mf=0;mf<2;mf++)
#pragma unroll
            for(int nf=0;nf<8;nf++)
#pragma unroll
                for(int hl=0;hl<2;hl++){
                    size_t idx = (size_t)(r0 + mf*16 + hl*8)*No + c0 + nf*8;
                    *(unsigned*)(O + idx) =
                        packhf(acc[mf][nf][hl*2]*scl, acc[mf][nf][hl*2+1]*scl);
                }
    }
}

// ---------------------------------------------------------------------------
// fp16 flash attention: q-tile 64, kv-tile 64, 2-stage, 3 CTAs/SM.
// 1 MMA per logical fragment. No-max exp2 softmax (scores bounded).
// ---------------------------------------------------------------------------
#define ASTR 72
#define A_Q  (64*ASTR)
#define A_MS (64*ASTR)
#define A_SS (2*A_MS)
#define ASMEM ((A_Q + 2*A_SS)*2)   // 46080 B

__global__ void __launch_bounds__(128,3)
attn_mma(const __half* __restrict__ Q1, const __half* __restrict__ K1,
         const __half* __restrict__ V1, __half* __restrict__ C1){
    extern __shared__ __half sm[];
    const unsigned smb = (unsigned)__cvta_generic_to_shared(sm);
    const int tid = threadIdx.x, lane = tid&31, wid = tid>>5;
    const int qt = blockIdx.x, bh = blockIdx.y;
    const int b = bh>>5, h = bh&31, kvh = h>>2;
    const int qbase = b*2048 + qt*64;
    const int kbase0 = b*2048;
    const int kvcol = kvh*64;

    // Q tile: 512 chunks / 128 thr = 4 iters
#pragma unroll
    for(int t=0;t<4;t++){
        int c = tid + t*128;
        int row = c>>3, ch = c&7;
        const __half* src = Q1 + (size_t)(qbase+row)*2048 + h*64 + ch*8;
        unsigned dst = smb + (unsigned)((row*ASTR)*2 + ch*16);
        cpa16(dst, src);
    }
    cpcommit();

    auto load_kv = [&](int s, int kt){
#pragma unroll
        for(int t=0;t<8;t++){
            int c = tid + t*128;
            int mat = c>>9, idx = c&511;
            int row = idx>>3, ch = idx&7;
            const __half* src = (mat ? V1 : K1) + (size_t)(kbase0 + kt*64 + row)*512 + kvcol + ch*8;
            unsigned dst = smb + (unsigned)((A_Q + s*A_SS + mat*A_MS + row*ASTR)*2 + ch*16);
            cpa16(dst, src);
        }
        cpcommit();
    };
    load_kv(0, 0);
    load_kv(1, 1);

    asm volatile("cp.async.wait_group 2;":::"memory");
    __syncthreads();

    unsigned aq[4][4];
    const unsigned qro = (unsigned)(((wid*16 + (lane&15))*ASTR)*2 + (lane>>4)*16);
#pragma unroll
    for(int ks=0;ks<4;ks++) ldsm4(aq[ks], smb + qro + ks*32);

    float od[8][4];
#pragma unroll
    for(int nf=0;nf<8;nf++)
#pragma unroll
        for(int q=0;q<4;q++) od[nf][q]=0.f;
    float l0=0.f, l1=0.f;

    const unsigned bro_col = (unsigned)(((lane>>3)&1)*16);
    const unsigned bro_row = (unsigned)((lane&7) + (lane>>4)*8);
    const unsigned tro_row = (unsigned)((lane&7) + ((lane>>3)&1)*8);
    const unsigned tro_col = (unsigned)((lane>>4)*16);

    for(int kt=0;kt<32;kt++){
        asm volatile("cp.async.wait_group 1;":::"memory");
        __syncthreads();
        unsigned sb = smb + (unsigned)((A_Q + (kt&1)*A_SS)*2);

        float sc[8][4];
#pragma unroll
        for(int nf=0;nf<8;nf++)
#pragma unroll
            for(int q=0;q<4;q++) sc[nf][q]=0.f;

#pragma unroll
        for(int ks=0;ks<4;ks++){
#pragma unroll
            for(int ng=0;ng<4;ng++){
                unsigned kh4[4];
                unsigned ro = (unsigned)((ng*16 + bro_row)*ASTR*2) + bro_col + ks*32;
                ldsm4(kh4, sb + ro);
                mmaf16(sc[ng*2+0], aq[ks], &kh4[0]);
                mmaf16(sc[ng*2+1], aq[ks], &kh4[2]);
            }
        }

#pragma unroll
        for(int ks=0;ks<4;ks++){
            unsigned aph[4];
#pragma unroll
            for(int q=0;q<4;q++){
                int nf = ks*2 + (q>>1);
                float v0 = ex2f(sc[nf][(q&1)*2]);
                float v1 = ex2f(sc[nf][(q&1)*2+1]);
                if(q&1) l1 += v0 + v1; else l0 += v0 + v1;
                aph[q] = packhf(v0, v1);
            }
#pragma unroll
            for(int dg=0;dg<4;dg++){
                unsigned vh4[4];
                unsigned ro = (unsigned)((ks*16 + tro_row)*ASTR*2) + dg*32 + tro_col;
                ldsm4t(vh4, sb + (unsigned)(A_MS*2) + ro);
                mmaf16(od[dg*2+0], aph, &vh4[0]);
                mmaf16(od[dg*2+1], aph, &vh4[2]);
            }
        }

        __syncthreads();
        if(kt+2 < 32) load_kv(kt&1, kt+2); else cpcommit();
    }

    l0 += __shfl_xor_sync(0xffffffffu, l0, 1);
    l0 += __shfl_xor_sync(0xffffffffu, l0, 2);
    l1 += __shfl_xor_sync(0xffffffffu, l1, 1);
    l1 += __shfl_xor_sync(0xffffffffu, l1, 2);
    float inv0 = 1.f/l0, inv1 = 1.f/l1;
    const int r = lane>>2, cb = (lane&3)*2;
    size_t i0 = (size_t)(qbase + wid*16 + r)*2048 + h*64 + cb;
    size_t i1 = i0 + (size_t)8*2048;
#pragma unroll
    for(int nf=0;nf<8;nf++){
        *(unsigned*)(C1 + i0 + nf*8) = packhf(od[nf][0]*inv0, od[nf][1]*inv0);
        *(unsigned*)(C1 + i1 + nf*8) = packhf(od[nf][2]*inv1, od[nf][3]*inv1);
    }
}

// ---- host ----
typedef CUresult (*tmap_fn_t)(CUtensorMap*, CUtensorMapDataType, cuuint32_t, void*,
                              const cuuint64_t*, const cuuint64_t*, const cuuint32_t*, const cuuint32_t*,
                              CUtensorMapInterleave, CUtensorMapSwizzle, CUtensorMapL2promotion, CUtensorMapFloatOOBfill);

static void make2d(tmap_fn_t enc, CUtensorMap* m, void* ptr, cuuint64_t rows){
    cuuint64_t dims[2] = {2048ull, rows};
    cuuint64_t strd[1] = {4096ull};
    cuuint32_t box[2] = {64u, 128u};
    cuuint32_t es[2] = {1u, 1u};
    enc(m, CU_TENSOR_MAP_DATA_TYPE_FLOAT16, 2, ptr, dims, strd, box, es,
        CU_TENSOR_MAP_INTERLEAVE_NONE, CU_TENSOR_MAP_SWIZZLE_128B,
        CU_TENSOR_MAP_L2_PROMOTION_L2_128B, CU_TENSOR_MAP_FLOAT_OOB_FILL_NONE);
}

extern "C" void kernel_launch(void* const* d_in, const int* in_sizes, int n_in,
                              void* d_out, int out_size){
    const float* x  = (const float*)d_in[0];
    const float* Wq = (const float*)d_in[1];
    const float* Wk = (const float*)d_in[2];
    const float* Wv = (const float*)d_in[3];
    const float* Wo = (const float*)d_in[4];
    float* out = (float*)d_out;

    void *xb,*wb,*wob,*q1,*k1,*v1;
    cudaGetSymbolAddress(&xb,g_x);
    cudaGetSymbolAddress(&wb,g_w);
    cudaGetSymbolAddress(&wob,g_wo);
    cudaGetSymbolAddress(&q1,g_q);
    cudaGetSymbolAddress(&k1,g_k);
    cudaGetSymbolAddress(&v1,g_v);

    tmap_fn_t enc = 0;
    cudaDriverEntryPointQueryResult qr;
    cudaGetDriverEntryPointByVersion("cuTensorMapEncodeTiled", (void**)&enc, 12000,
                                     cudaEnableDefault, &qr);

    static CUtensorMap tX,tW,tWo;
    make2d(enc,&tX,xb,4096);
    make2d(enc,&tW,wb,3072);
    make2d(enc,&tWo,wob,2048);

    cudaFuncSetAttribute(gemm_tma, cudaFuncAttributeMaxDynamicSharedMemorySize, GSMEM);
    cudaFuncSetAttribute(attn_mma, cudaFuncAttributeMaxDynamicSharedMemorySize, ASMEM);

    wtruncAll<<<dim3(160,64),dim3(32,8)>>>(Wq, Wk, Wv, Wo, (__half*)wb, (__half*)wob);
    ftrunc<<<512,256>>>((const float4*)x, (uint2*)xb, 4096*2048/4);

    // fused QKV projection
    gemm_tma<<<dim3(24,32),256,GSMEM>>>(tX,tW, nullptr,
        (__half*)q1, (__half*)k1, (__half*)v1);

    // attention -> ctx (reuse g_x)
    attn_mma<<<dim3(32,64),128,ASMEM>>>((__half*)q1, (__half*)k1, (__half*)v1, (__half*)xb);

    // O projection -> fp32 out
    gemm_tma<<<dim3(16,32),256,GSMEM>>>(tX,tWo, out, nullptr,nullptr,nullptr);
}